// round 1
// baseline (speedup 1.0000x reference)
#include <cuda_runtime.h>
#include <cuda_bf16.h>
#include <cstdint>

// ---------------------------------------------------------------------------
// Attention_32186484917066
//   x[1,4096,1024] --Wqkv,bqkv--> qkv[4096,3072]
//   split into Q/K/V, 16 heads x 64 dims, causal softmax attention
//   merge heads --Wproj,bproj--> out[4096,1024]
// All fp32. Baseline: FMA-pipe SGEMMs + fp32 flash attention.
// ---------------------------------------------------------------------------

#define SEQ    4096
#define DMODEL 1024
#define NHEAD  16
#define HDIM   64
#define N_QKV  3072

// Scratch (allocation-free rule: __device__ globals)
// qkv laid out as [part(3)][head(16)][seq(4096)][dim(64)]
__device__ float g_qkv[3 * NHEAD * SEQ * HDIM];
// attention output merged heads: [seq][dmodel]
__device__ float g_att[SEQ * DMODEL];

// ---------------------------------------------------------------------------
// SGEMM: C = A[M,K] @ B[K,N] + bias, 128x128x8 tile, 8x8/thread, 256 threads
// ---------------------------------------------------------------------------
#define BM 128
#define BN 128
#define BK 8
#define TM 8
#define TN 8

// GEMM1: qkv = x @ Wqkv + bqkv, stored permuted into g_qkv
__global__ __launch_bounds__(256) void gemm_qkv_kernel(
    const float* __restrict__ A,     // x [4096,1024]
    const float* __restrict__ B,     // Wqkv [1024,3072]
    const float* __restrict__ bias)  // bqkv [3072]
{
    __shared__ float As[BK][BM];
    __shared__ float Bs[BK][BN];

    const int K = DMODEL, N = N_QKV;
    const int tid = threadIdx.x;
    const int tx = tid % 16, ty = tid / 16;
    const int bm = blockIdx.y * BM, bn = blockIdx.x * BN;

    const int arow = tid / 2;         // 0..127
    const int acol = (tid % 2) * 4;   // 0 or 4
    const int brow = tid / 32;        // 0..7
    const int bcol = (tid % 32) * 4;  // 0..124

    const float* Aptr = A + (size_t)(bm + arow) * K + acol;
    const float* Bptr = B + (size_t)brow * N + bn + bcol;

    float acc[TM][TN] = {};

    for (int k0 = 0; k0 < K; k0 += BK) {
        float4 av = *(const float4*)Aptr;  Aptr += BK;
        float4 bv = *(const float4*)Bptr;  Bptr += (size_t)BK * N;
        As[acol + 0][arow] = av.x;
        As[acol + 1][arow] = av.y;
        As[acol + 2][arow] = av.z;
        As[acol + 3][arow] = av.w;
        *(float4*)&Bs[brow][bcol] = bv;
        __syncthreads();

        #pragma unroll
        for (int k = 0; k < BK; k++) {
            float a[TM], b[TN];
            *(float4*)(a)     = *(float4*)&As[k][ty * TM];
            *(float4*)(a + 4) = *(float4*)&As[k][ty * TM + 4];
            *(float4*)(b)     = *(float4*)&Bs[k][tx * TN];
            *(float4*)(b + 4) = *(float4*)&Bs[k][tx * TN + 4];
            #pragma unroll
            for (int i = 0; i < TM; i++)
                #pragma unroll
                for (int j = 0; j < TN; j++)
                    acc[i][j] += a[i] * b[j];
        }
        __syncthreads();
    }

    // Epilogue: add bias, permute into g_qkv[part][head][seq][dim]
    #pragma unroll
    for (int i = 0; i < TM; i++) {
        const int r = bm + ty * TM + i;
        #pragma unroll
        for (int jj = 0; jj < TN; jj += 4) {
            const int n = bn + tx * TN + jj;       // within one head (8|64)
            const int part = n >> 10;              // /1024
            const int h    = (n & 1023) >> 6;      // /64
            const int d    = n & 63;
            const float4 bsv = *(const float4*)&bias[n];
            float4 v;
            v.x = acc[i][jj + 0] + bsv.x;
            v.y = acc[i][jj + 1] + bsv.y;
            v.z = acc[i][jj + 2] + bsv.z;
            v.w = acc[i][jj + 3] + bsv.w;
            *(float4*)&g_qkv[(((size_t)(part * NHEAD + h) * SEQ + r) << 6) + d] = v;
        }
    }
}

// GEMM2: out = g_att @ Wproj + bproj
__global__ __launch_bounds__(256) void gemm_proj_kernel(
    const float* __restrict__ B,     // Wproj [1024,1024]
    const float* __restrict__ bias,  // bproj [1024]
    float* __restrict__ out)         // [4096,1024]
{
    __shared__ float As[BK][BM];
    __shared__ float Bs[BK][BN];

    const int K = DMODEL, N = DMODEL;
    const int tid = threadIdx.x;
    const int tx = tid % 16, ty = tid / 16;
    const int bm = blockIdx.y * BM, bn = blockIdx.x * BN;

    const int arow = tid / 2;
    const int acol = (tid % 2) * 4;
    const int brow = tid / 32;
    const int bcol = (tid % 32) * 4;

    const float* Aptr = g_att + (size_t)(bm + arow) * K + acol;
    const float* Bptr = B + (size_t)brow * N + bn + bcol;

    float acc[TM][TN] = {};

    for (int k0 = 0; k0 < K; k0 += BK) {
        float4 av = *(const float4*)Aptr;  Aptr += BK;
        float4 bv = *(const float4*)Bptr;  Bptr += (size_t)BK * N;
        As[acol + 0][arow] = av.x;
        As[acol + 1][arow] = av.y;
        As[acol + 2][arow] = av.z;
        As[acol + 3][arow] = av.w;
        *(float4*)&Bs[brow][bcol] = bv;
        __syncthreads();

        #pragma unroll
        for (int k = 0; k < BK; k++) {
            float a[TM], b[TN];
            *(float4*)(a)     = *(float4*)&As[k][ty * TM];
            *(float4*)(a + 4) = *(float4*)&As[k][ty * TM + 4];
            *(float4*)(b)     = *(float4*)&Bs[k][tx * TN];
            *(float4*)(b + 4) = *(float4*)&Bs[k][tx * TN + 4];
            #pragma unroll
            for (int i = 0; i < TM; i++)
                #pragma unroll
                for (int j = 0; j < TN; j++)
                    acc[i][j] += a[i] * b[j];
        }
        __syncthreads();
    }

    #pragma unroll
    for (int i = 0; i < TM; i++) {
        const int r = bm + ty * TM + i;
        #pragma unroll
        for (int jj = 0; jj < TN; jj += 4) {
            const int n = bn + tx * TN + jj;
            const float4 bsv = *(const float4*)&bias[n];
            float4 v;
            v.x = acc[i][jj + 0] + bsv.x;
            v.y = acc[i][jj + 1] + bsv.y;
            v.z = acc[i][jj + 2] + bsv.z;
            v.w = acc[i][jj + 3] + bsv.w;
            *(float4*)&out[(size_t)r * N + n] = v;
        }
    }
}

// ---------------------------------------------------------------------------
// Flash attention (fp32): one CTA per (query tile of 64 rows, head).
// 64x64 tiles, 4x4 register micro-tiles, online softmax via half-warp
// butterfly reductions. P is written back into the K smem buffer.
// ---------------------------------------------------------------------------
__global__ __launch_bounds__(256) void attn_kernel()
{
    const int qt = 63 - blockIdx.x;   // big tiles first (tail balance)
    const int h  = blockIdx.y;

    const float* Q = g_qkv + (size_t)(0 * NHEAD + h) * SEQ * HDIM;
    const float* K = g_qkv + (size_t)(1 * NHEAD + h) * SEQ * HDIM;
    const float* V = g_qkv + (size_t)(2 * NHEAD + h) * SEQ * HDIM;

    __shared__ float Qs[64][64];  // [d][r]
    __shared__ float Ks[64][64];  // [d][c]; reused as Ps[c][r]
    __shared__ float Vs[64][64];  // [c][d]

    const int tid = threadIdx.x;
    const int tx = tid % 16, ty = tid / 16;
    const int r0 = ty * 4;        // query rows (tile-local)
    const int c0 = tx * 4;        // key cols / output dims (tile-local)

    // Load Q tile transposed: Qs[d][r]
    {
        const int r  = tid % 64;
        const int db = (tid / 64) * 4;
        const float* qrow = Q + (size_t)(qt * 64 + r) * HDIM;
        #pragma unroll
        for (int dd = 0; dd < 64; dd += 16) {
            float4 v = *(const float4*)(qrow + db + dd);
            Qs[db + dd + 0][r] = v.x;
            Qs[db + dd + 1][r] = v.y;
            Qs[db + dd + 2][r] = v.z;
            Qs[db + dd + 3][r] = v.w;
        }
    }

    float O[4][4] = {};
    float m[4], l[4];
    #pragma unroll
    for (int i = 0; i < 4; i++) { m[i] = -1e30f; l[i] = 0.0f; }

    const float scale = 0.125f;  // 1/sqrt(64)

    for (int kt = 0; kt <= qt; kt++) {
        __syncthreads();  // prior PV done reading Ks/Vs (and Qs ready, kt=0)

        // Load K transposed -> Ks[d][c], V natural -> Vs[c][d]
        {
            const int c  = tid % 64;
            const int db = (tid / 64) * 4;
            const float* krow = K + (size_t)(kt * 64 + c) * HDIM;
            const float* vrow = V + (size_t)(kt * 64 + c) * HDIM;
            #pragma unroll
            for (int dd = 0; dd < 64; dd += 16) {
                float4 kv = *(const float4*)(krow + db + dd);
                Ks[db + dd + 0][c] = kv.x;
                Ks[db + dd + 1][c] = kv.y;
                Ks[db + dd + 2][c] = kv.z;
                Ks[db + dd + 3][c] = kv.w;
                *(float4*)&Vs[c][db + dd] = *(const float4*)(vrow + db + dd);
            }
        }
        __syncthreads();

        // S = (Q K^T) * scale
        float S[4][4] = {};
        #pragma unroll 8
        for (int d = 0; d < 64; d++) {
            float a[4], b[4];
            *(float4*)a = *(float4*)&Qs[d][r0];
            *(float4*)b = *(float4*)&Ks[d][c0];
            #pragma unroll
            for (int i = 0; i < 4; i++)
                #pragma unroll
                for (int j = 0; j < 4; j++)
                    S[i][j] += a[i] * b[j];
        }

        const bool diag = (kt == qt);
        #pragma unroll
        for (int i = 0; i < 4; i++)
            #pragma unroll
            for (int j = 0; j < 4; j++) {
                float s = S[i][j] * scale;
                if (diag && (c0 + j) > (r0 + i)) s = -1e30f;
                S[i][j] = s;
            }

        // Online softmax: half-warp (16 col-threads per row group) butterflies
        #pragma unroll
        for (int i = 0; i < 4; i++) {
            float rmax = fmaxf(fmaxf(S[i][0], S[i][1]), fmaxf(S[i][2], S[i][3]));
            #pragma unroll
            for (int s = 1; s < 16; s <<= 1)
                rmax = fmaxf(rmax, __shfl_xor_sync(0xffffffffu, rmax, s));

            const float mn = fmaxf(m[i], rmax);
            const float sc = __expf(m[i] - mn);
            m[i] = mn;
            l[i] *= sc;
            #pragma unroll
            for (int j = 0; j < 4; j++) O[i][j] *= sc;

            float rs = 0.0f;
            #pragma unroll
            for (int j = 0; j < 4; j++) {
                float p = __expf(S[i][j] - mn);
                S[i][j] = p;
                rs += p;
            }
            #pragma unroll
            for (int s = 1; s < 16; s <<= 1)
                rs += __shfl_xor_sync(0xffffffffu, rs, s);
            l[i] += rs;
        }

        __syncthreads();  // everyone done reading Ks before reuse as Ps

        // Write P transposed into Ks: Ps[c][r]
        #pragma unroll
        for (int j = 0; j < 4; j++) {
            float4 pv;
            pv.x = S[0][j]; pv.y = S[1][j]; pv.z = S[2][j]; pv.w = S[3][j];
            *(float4*)&Ks[c0 + j][r0] = pv;
        }
        __syncthreads();

        // O += P @ V
        #pragma unroll 8
        for (int c = 0; c < 64; c++) {
            float a[4], b[4];
            *(float4*)a = *(float4*)&Ks[c][r0];  // P[r][c]
            *(float4*)b = *(float4*)&Vs[c][c0];
            #pragma unroll
            for (int i = 0; i < 4; i++)
                #pragma unroll
                for (int j = 0; j < 4; j++)
                    O[i][j] += a[i] * b[j];
        }
    }

    // Normalize and store merged-head layout [seq][dmodel]
    #pragma unroll
    for (int i = 0; i < 4; i++) {
        const float inv = 1.0f / l[i];
        const int r = qt * 64 + r0 + i;
        float4 ov;
        ov.x = O[i][0] * inv; ov.y = O[i][1] * inv;
        ov.z = O[i][2] * inv; ov.w = O[i][3] * inv;
        *(float4*)&g_att[(size_t)r * DMODEL + h * HDIM + c0] = ov;
    }
}

// ---------------------------------------------------------------------------
extern "C" void kernel_launch(void* const* d_in, const int* in_sizes, int n_in,
                              void* d_out, int out_size)
{
    const float* x     = (const float*)d_in[0];
    const float* Wqkv  = (const float*)d_in[1];
    const float* bqkv  = (const float*)d_in[2];
    const float* Wproj = (const float*)d_in[3];
    const float* bproj = (const float*)d_in[4];
    float* out = (float*)d_out;

    // GEMM1: qkv = x @ Wqkv + bqkv  -> g_qkv (permuted)
    {
        dim3 grid(N_QKV / BN, SEQ / BM);
        gemm_qkv_kernel<<<grid, 256>>>(x, Wqkv, bqkv);
    }
    // Flash attention -> g_att
    {
        dim3 grid(SEQ / 64, NHEAD);
        attn_kernel<<<grid, 256>>>();
    }
    // GEMM2: out = g_att @ Wproj + bproj
    {
        dim3 grid(DMODEL / BN, SEQ / BM);
        gemm_proj_kernel<<<grid, 256>>>(Wproj, bproj, out);
    }
}

// round 3
// speedup vs baseline: 1.2179x; 1.2179x over previous
#include <cuda_runtime.h>
#include <cuda_bf16.h>
#include <cstdint>

// ---------------------------------------------------------------------------
// Attention_32186484917066 — R3: GEMMs on mma.sync bf16 (split hi/lo, 3-MMA),
// attention fp32 (unchanged from R1). tcgen05 is unusable: harness targets
// sm_103 (no 'a'), which rejects arch-accelerated instructions.
// ---------------------------------------------------------------------------

#define SEQ    4096
#define DMODEL 1024
#define NHEAD  16
#define HDIM   64
#define N_QKV  3072

// ------------------------- device scratch (no allocs) -----------------------
__device__ __align__(16) __nv_bfloat16 g_xhi[SEQ * DMODEL];
__device__ __align__(16) __nv_bfloat16 g_xlo[SEQ * DMODEL];
__device__ __align__(16) __nv_bfloat16 g_wqkvT_hi[N_QKV * DMODEL];   // [N][K]
__device__ __align__(16) __nv_bfloat16 g_wqkvT_lo[N_QKV * DMODEL];
__device__ __align__(16) __nv_bfloat16 g_wprojT_hi[DMODEL * DMODEL]; // [N][K]
__device__ __align__(16) __nv_bfloat16 g_wprojT_lo[DMODEL * DMODEL];
__device__ float g_qkv[3 * NHEAD * SEQ * HDIM];  // [part][head][seq][dim] fp32
__device__ __align__(16) __nv_bfloat16 g_att_hi[SEQ * DMODEL];
__device__ __align__(16) __nv_bfloat16 g_att_lo[SEQ * DMODEL];

// ------------------------- helpers -----------------------------------------
__device__ __forceinline__ uint32_t smem_u32(const void* p) {
    uint32_t a;
    asm("{ .reg .u64 t; cvta.to.shared.u64 t, %1; cvt.u32.u64 %0, t; }" : "=r"(a) : "l"(p));
    return a;
}
#define CP_ASYNC16(s, g) \
    asm volatile("cp.async.cg.shared.global [%0], [%1], 16;" :: "r"(s), "l"(g))
#define CP_COMMIT()  asm volatile("cp.async.commit_group;" ::: "memory")
#define CP_WAIT(n)   asm volatile("cp.async.wait_group %0;" :: "n"(n) : "memory")

__device__ __forceinline__ void mma16816(float* c, const uint32_t* a,
                                         uint32_t b0, uint32_t b1) {
    asm volatile(
        "mma.sync.aligned.m16n8k16.row.col.f32.bf16.bf16.f32 "
        "{%0,%1,%2,%3}, {%4,%5,%6,%7}, {%8,%9}, {%0,%1,%2,%3};"
        : "+f"(c[0]), "+f"(c[1]), "+f"(c[2]), "+f"(c[3])
        : "r"(a[0]), "r"(a[1]), "r"(a[2]), "r"(a[3]), "r"(b0), "r"(b1));
}

// ------------------------- conversion kernels ------------------------------
__global__ __launch_bounds__(256) void convert_split_kernel(
    const float* __restrict__ in, __nv_bfloat16* __restrict__ hi,
    __nv_bfloat16* __restrict__ lo, int n4)
{
    int i = blockIdx.x * 256 + threadIdx.x;
    if (i >= n4) return;
    float4 v = ((const float4*)in)[i];
    float vv[4] = {v.x, v.y, v.z, v.w};
    ushort4 h, l;
    unsigned short* hp = (unsigned short*)&h;
    unsigned short* lp = (unsigned short*)&l;
    #pragma unroll
    for (int j = 0; j < 4; j++) {
        __nv_bfloat16 bh = __float2bfloat16(vv[j]);
        float rem = vv[j] - __bfloat162float(bh);
        __nv_bfloat16 bl = __float2bfloat16(rem);
        hp[j] = *(unsigned short*)&bh;
        lp[j] = *(unsigned short*)&bl;
    }
    ((ushort4*)hi)[i] = h;
    ((ushort4*)lo)[i] = l;
}

// W[K][N] fp32 -> hi/lo [N][K] bf16 (transpose + split)
__global__ __launch_bounds__(256) void convert_transpose_kernel(
    const float* __restrict__ W, __nv_bfloat16* __restrict__ hi,
    __nv_bfloat16* __restrict__ lo, int K, int N)
{
    __shared__ float t[32][33];
    const int bn = blockIdx.x * 32, bk = blockIdx.y * 32;
    const int tx = threadIdx.x & 31, ty = threadIdx.x >> 5; // 32 x 8
    #pragma unroll
    for (int r = 0; r < 32; r += 8)
        t[r + ty][tx] = W[(size_t)(bk + r + ty) * N + bn + tx];
    __syncthreads();
    #pragma unroll
    for (int r = 0; r < 32; r += 8) {
        float v = t[tx][r + ty];
        __nv_bfloat16 bh = __float2bfloat16(v);
        float rem = v - __bfloat162float(bh);
        __nv_bfloat16 bl = __float2bfloat16(rem);
        size_t o = (size_t)(bn + r + ty) * K + bk + tx;
        hi[o] = bh;
        lo[o] = bl;
    }
}

// ------------------------- mma.sync GEMM ------------------------------------
// C[4096, N] = A[4096,1024] @ B^T (B stored [N][1024]) via split-bf16 3-MMA.
// CTA tile 128x128, BK=32, 8 warps (warp tile 32x64), cp.async double buffer.
// smem mat layout: [128 rows][40 halves] (pad 32->40 => conflict-free frags).

#define GK       DMODEL
#define KITERS   (GK / 32)
#define MAT_B    (128 * 40 * 2)   // 10240 bytes
#define STAGE_B  (4 * MAT_B)      // 40960 bytes
#define DYN_SMEM (2 * STAGE_B)    // 81920 bytes

template <bool QKV>
__global__ __launch_bounds__(256, 1) void mma_gemm_kernel(
    const __nv_bfloat16* __restrict__ Ahi, const __nv_bfloat16* __restrict__ Alo,
    const __nv_bfloat16* __restrict__ Bhi, const __nv_bfloat16* __restrict__ Blo,
    const float* __restrict__ bias, float* __restrict__ out, int N)
{
    extern __shared__ char sm[];
    const uint32_t sb = smem_u32(sm);

    const int tid  = threadIdx.x;
    const int lane = tid & 31;
    const int wid  = tid >> 5;
    const int gid  = lane >> 2;   // 0..7
    const int tig  = lane & 3;    // 0..3
    const int wm   = wid & 3;     // warp row  (4 x 32 = 128)
    const int wn   = wid >> 2;    // warp col  (2 x 64 = 128)

    const int bm = blockIdx.y * 128;
    const int bn = blockIdx.x * 128;

    // issue cp.async for one stage (4 mats x 128 rows x 64B)
    auto issue_stage = [&](int stage, int kt) {
        const uint32_t stb = sb + stage * STAGE_B;
        #pragma unroll
        for (int mat = 0; mat < 4; mat++) {
            const __nv_bfloat16* base =
                (mat == 0) ? Ahi : (mat == 1) ? Alo : (mat == 2) ? Bhi : Blo;
            const int r0 = (mat < 2) ? bm : bn;
            #pragma unroll
            for (int p = 0; p < 2; p++) {
                const int idx = p * 256 + tid;     // 0..511
                const int row = idx >> 2;
                const int c   = idx & 3;
                const char* g = (const char*)(base + (size_t)(r0 + row) * GK
                                              + kt * 32 + c * 8);
                CP_ASYNC16(stb + mat * MAT_B + row * 80 + c * 16, g);
            }
        }
    };

    float acc[2][8][4] = {};

    issue_stage(0, 0);
    CP_COMMIT();

    for (int kt = 0; kt < KITERS; kt++) {
        if (kt + 1 < KITERS) {
            issue_stage((kt + 1) & 1, kt + 1);
            CP_COMMIT();
            CP_WAIT(1);
        } else {
            CP_WAIT(0);
        }
        __syncthreads();

        const char* stg = sm + (kt & 1) * STAGE_B;
        const char* sAh = stg;
        const char* sAl = stg + MAT_B;
        const char* sBh = stg + 2 * MAT_B;
        const char* sBl = stg + 3 * MAT_B;

        #pragma unroll
        for (int ks = 0; ks < 2; ks++) {
            const int colb = (ks * 16 + tig * 2) * 2;  // byte offset of k-pair

            uint32_t ah[2][4], al[2][4];
            #pragma unroll
            for (int mt = 0; mt < 2; mt++) {
                const int row = wm * 32 + mt * 16 + gid;
                ah[mt][0] = *(const uint32_t*)(sAh + row * 80 + colb);
                ah[mt][1] = *(const uint32_t*)(sAh + (row + 8) * 80 + colb);
                ah[mt][2] = *(const uint32_t*)(sAh + row * 80 + colb + 16);
                ah[mt][3] = *(const uint32_t*)(sAh + (row + 8) * 80 + colb + 16);
                al[mt][0] = *(const uint32_t*)(sAl + row * 80 + colb);
                al[mt][1] = *(const uint32_t*)(sAl + (row + 8) * 80 + colb);
                al[mt][2] = *(const uint32_t*)(sAl + row * 80 + colb + 16);
                al[mt][3] = *(const uint32_t*)(sAl + (row + 8) * 80 + colb + 16);
            }
            #pragma unroll
            for (int nt = 0; nt < 8; nt++) {
                const int nrow = wn * 64 + nt * 8 + gid;
                const uint32_t bh0 = *(const uint32_t*)(sBh + nrow * 80 + colb);
                const uint32_t bh1 = *(const uint32_t*)(sBh + nrow * 80 + colb + 16);
                const uint32_t bl0 = *(const uint32_t*)(sBl + nrow * 80 + colb);
                const uint32_t bl1 = *(const uint32_t*)(sBl + nrow * 80 + colb + 16);
                #pragma unroll
                for (int mt = 0; mt < 2; mt++) {
                    mma16816(acc[mt][nt], ah[mt], bh0, bh1);
                    mma16816(acc[mt][nt], ah[mt], bl0, bl1);
                    mma16816(acc[mt][nt], al[mt], bh0, bh1);
                }
            }
        }
        __syncthreads();
    }

    // epilogue
    #pragma unroll
    for (int mt = 0; mt < 2; mt++) {
        const int r = bm + wm * 32 + mt * 16 + gid;
        #pragma unroll
        for (int nt = 0; nt < 8; nt++) {
            const int col = bn + wn * 64 + nt * 8 + tig * 2;
            const float2 bv = *(const float2*)&bias[col];
            float2 d0, d1;
            d0.x = acc[mt][nt][0] + bv.x;
            d0.y = acc[mt][nt][1] + bv.y;
            d1.x = acc[mt][nt][2] + bv.x;
            d1.y = acc[mt][nt][3] + bv.y;
            if (QKV) {
                const int part = col >> 10;
                const int h = (col >> 6) & 15;
                const int d = col & 63;
                float* dst = g_qkv + (((size_t)(part * NHEAD + h) * SEQ + r) << 6) + d;
                *(float2*)dst = d0;
                *(float2*)(dst + 8 * 64) = d1;   // row r+8
            } else {
                float* dst = out + (size_t)r * N + col;
                *(float2*)dst = d0;
                *(float2*)(dst + 8 * (size_t)N) = d1;
            }
        }
    }
}

// ---------------------------------------------------------------------------
// Flash attention (fp32): proven R1 kernel, epilogue emits split-bf16.
// ---------------------------------------------------------------------------
__global__ __launch_bounds__(256) void attn_kernel()
{
    const int qt = 63 - blockIdx.x;
    const int h = blockIdx.y;

    const float* Q = g_qkv + (size_t)(0 * NHEAD + h) * SEQ * HDIM;
    const float* K = g_qkv + (size_t)(1 * NHEAD + h) * SEQ * HDIM;
    const float* V = g_qkv + (size_t)(2 * NHEAD + h) * SEQ * HDIM;

    __shared__ float Qs[64][64];
    __shared__ float Ks[64][64];
    __shared__ float Vs[64][64];

    const int tid = threadIdx.x;
    const int tx = tid % 16, ty = tid / 16;
    const int r0 = ty * 4;
    const int c0 = tx * 4;

    {
        const int r = tid % 64;
        const int db = (tid / 64) * 4;
        const float* qrow = Q + (size_t)(qt * 64 + r) * HDIM;
        #pragma unroll
        for (int dd = 0; dd < 64; dd += 16) {
            float4 v = *(const float4*)(qrow + db + dd);
            Qs[db + dd + 0][r] = v.x;
            Qs[db + dd + 1][r] = v.y;
            Qs[db + dd + 2][r] = v.z;
            Qs[db + dd + 3][r] = v.w;
        }
    }

    float O[4][4] = {};
    float m[4], l[4];
    #pragma unroll
    for (int i = 0; i < 4; i++) { m[i] = -1e30f; l[i] = 0.0f; }

    const float scale = 0.125f;

    for (int kt = 0; kt <= qt; kt++) {
        __syncthreads();
        {
            const int c = tid % 64;
            const int db = (tid / 64) * 4;
            const float* krow = K + (size_t)(kt * 64 + c) * HDIM;
            const float* vrow = V + (size_t)(kt * 64 + c) * HDIM;
            #pragma unroll
            for (int dd = 0; dd < 64; dd += 16) {
                float4 kv = *(const float4*)(krow + db + dd);
                Ks[db + dd + 0][c] = kv.x;
                Ks[db + dd + 1][c] = kv.y;
                Ks[db + dd + 2][c] = kv.z;
                Ks[db + dd + 3][c] = kv.w;
                *(float4*)&Vs[c][db + dd] = *(const float4*)(vrow + db + dd);
            }
        }
        __syncthreads();

        float S[4][4] = {};
        #pragma unroll 8
        for (int d = 0; d < 64; d++) {
            float a[4], b[4];
            *(float4*)a = *(float4*)&Qs[d][r0];
            *(float4*)b = *(float4*)&Ks[d][c0];
            #pragma unroll
            for (int i = 0; i < 4; i++)
                #pragma unroll
                for (int j = 0; j < 4; j++)
                    S[i][j] += a[i] * b[j];
        }

        const bool diag = (kt == qt);
        #pragma unroll
        for (int i = 0; i < 4; i++)
            #pragma unroll
            for (int j = 0; j < 4; j++) {
                float s = S[i][j] * scale;
                if (diag && (c0 + j) > (r0 + i)) s = -1e30f;
                S[i][j] = s;
            }

        #pragma unroll
        for (int i = 0; i < 4; i++) {
            float rmax = fmaxf(fmaxf(S[i][0], S[i][1]), fmaxf(S[i][2], S[i][3]));
            #pragma unroll
            for (int s = 1; s < 16; s <<= 1)
                rmax = fmaxf(rmax, __shfl_xor_sync(0xffffffffu, rmax, s));

            const float mn = fmaxf(m[i], rmax);
            const float sc = __expf(m[i] - mn);
            m[i] = mn;
            l[i] *= sc;
            #pragma unroll
            for (int j = 0; j < 4; j++) O[i][j] *= sc;

            float rs = 0.0f;
            #pragma unroll
            for (int j = 0; j < 4; j++) {
                float p = __expf(S[i][j] - mn);
                S[i][j] = p;
                rs += p;
            }
            #pragma unroll
            for (int s = 1; s < 16; s <<= 1)
                rs += __shfl_xor_sync(0xffffffffu, rs, s);
            l[i] += rs;
        }

        __syncthreads();
        #pragma unroll
        for (int j = 0; j < 4; j++) {
            float4 pv;
            pv.x = S[0][j]; pv.y = S[1][j]; pv.z = S[2][j]; pv.w = S[3][j];
            *(float4*)&Ks[c0 + j][r0] = pv;
        }
        __syncthreads();

        #pragma unroll 8
        for (int c = 0; c < 64; c++) {
            float a[4], b[4];
            *(float4*)a = *(float4*)&Ks[c][r0];
            *(float4*)b = *(float4*)&Vs[c][c0];
            #pragma unroll
            for (int i = 0; i < 4; i++)
                #pragma unroll
                for (int j = 0; j < 4; j++)
                    O[i][j] += a[i] * b[j];
        }
    }

    // epilogue: split-bf16 (hi/lo) for GEMM2
    #pragma unroll
    for (int i = 0; i < 4; i++) {
        const float inv = 1.0f / l[i];
        const int r = qt * 64 + r0 + i;
        ushort4 hs, ls;
        unsigned short* hp = (unsigned short*)&hs;
        unsigned short* lp = (unsigned short*)&ls;
        #pragma unroll
        for (int j = 0; j < 4; j++) {
            float v = O[i][j] * inv;
            __nv_bfloat16 bh = __float2bfloat16(v);
            float rem = v - __bfloat162float(bh);
            __nv_bfloat16 bl = __float2bfloat16(rem);
            hp[j] = *(unsigned short*)&bh;
            lp[j] = *(unsigned short*)&bl;
        }
        const size_t o = (size_t)r * DMODEL + h * HDIM + c0;
        *(ushort4*)&g_att_hi[o] = hs;
        *(ushort4*)&g_att_lo[o] = ls;
    }
}

// ---------------------------------------------------------------------------
extern "C" void kernel_launch(void* const* d_in, const int* in_sizes, int n_in,
                              void* d_out, int out_size)
{
    const float* x     = (const float*)d_in[0];
    const float* Wqkv  = (const float*)d_in[1];
    const float* bqkv  = (const float*)d_in[2];
    const float* Wproj = (const float*)d_in[3];
    const float* bproj = (const float*)d_in[4];
    float* out = (float*)d_out;

    static bool attr_done = false;
    if (!attr_done) {
        cudaFuncSetAttribute(mma_gemm_kernel<true>,
                             cudaFuncAttributeMaxDynamicSharedMemorySize, DYN_SMEM);
        cudaFuncSetAttribute(mma_gemm_kernel<false>,
                             cudaFuncAttributeMaxDynamicSharedMemorySize, DYN_SMEM);
        attr_done = true;
    }

    __nv_bfloat16 *xhi, *xlo, *wqh, *wql, *wph, *wpl, *ahi, *alo;
    cudaGetSymbolAddress((void**)&xhi, g_xhi);
    cudaGetSymbolAddress((void**)&xlo, g_xlo);
    cudaGetSymbolAddress((void**)&wqh, g_wqkvT_hi);
    cudaGetSymbolAddress((void**)&wql, g_wqkvT_lo);
    cudaGetSymbolAddress((void**)&wph, g_wprojT_hi);
    cudaGetSymbolAddress((void**)&wpl, g_wprojT_lo);
    cudaGetSymbolAddress((void**)&ahi, g_att_hi);
    cudaGetSymbolAddress((void**)&alo, g_att_lo);

    // 1) conversions
    convert_split_kernel<<<(SEQ * DMODEL / 4 + 255) / 256, 256>>>(x, xhi, xlo,
                                                                  SEQ * DMODEL / 4);
    convert_transpose_kernel<<<dim3(N_QKV / 32, DMODEL / 32), 256>>>(Wqkv, wqh, wql,
                                                                     DMODEL, N_QKV);
    convert_transpose_kernel<<<dim3(DMODEL / 32, DMODEL / 32), 256>>>(Wproj, wph, wpl,
                                                                      DMODEL, DMODEL);
    // 2) GEMM1: qkv = x @ Wqkv + bqkv -> g_qkv (permuted fp32)
    mma_gemm_kernel<true><<<dim3(N_QKV / 128, SEQ / 128), 256, DYN_SMEM>>>(
        xhi, xlo, wqh, wql, bqkv, nullptr, N_QKV);
    // 3) attention (fp32) -> g_att_hi/lo
    attn_kernel<<<dim3(SEQ / 64, NHEAD), 256>>>();
    // 4) GEMM2: out = att @ Wproj + bproj
    mma_gemm_kernel<false><<<dim3(DMODEL / 128, SEQ / 128), 256, DYN_SMEM>>>(
        ahi, alo, wph, wpl, bproj, out, DMODEL);
}

// round 4
// speedup vs baseline: 3.0989x; 2.5444x over previous
#include <cuda_runtime.h>
#include <cuda_bf16.h>
#include <cstdint>

// ---------------------------------------------------------------------------
// Attention_32186484917066 — R4: everything on mma.sync bf16 (split hi/lo).
// GEMM1/GEMM2 unchanged from R3 (passed). Attention now flash-style with
// m16n8k16 MMAs: QK^T 3-MMA split, PV 3-MMA split, exp2 softmax.
// ---------------------------------------------------------------------------

#define SEQ    4096
#define DMODEL 1024
#define NHEAD  16
#define HDIM   64
#define N_QKV  3072

// ------------------------- device scratch (no allocs) -----------------------
__device__ __align__(16) __nv_bfloat16 g_xhi[SEQ * DMODEL];
__device__ __align__(16) __nv_bfloat16 g_xlo[SEQ * DMODEL];
__device__ __align__(16) __nv_bfloat16 g_wqkvT_hi[N_QKV * DMODEL];   // [N][K]
__device__ __align__(16) __nv_bfloat16 g_wqkvT_lo[N_QKV * DMODEL];
__device__ __align__(16) __nv_bfloat16 g_wprojT_hi[DMODEL * DMODEL]; // [N][K]
__device__ __align__(16) __nv_bfloat16 g_wprojT_lo[DMODEL * DMODEL];
__device__ float g_qkv[3 * NHEAD * SEQ * HDIM];  // [part][head][seq][dim] fp32
__device__ __align__(16) __nv_bfloat16 g_att_hi[SEQ * DMODEL];
__device__ __align__(16) __nv_bfloat16 g_att_lo[SEQ * DMODEL];
// attention operands (split bf16)
__device__ __align__(16) __nv_bfloat16 g_q_hi[NHEAD * SEQ * HDIM];   // [h][s][d]
__device__ __align__(16) __nv_bfloat16 g_q_lo[NHEAD * SEQ * HDIM];
__device__ __align__(16) __nv_bfloat16 g_k_hi[NHEAD * SEQ * HDIM];   // [h][s][d]
__device__ __align__(16) __nv_bfloat16 g_k_lo[NHEAD * SEQ * HDIM];
__device__ __align__(16) __nv_bfloat16 g_vt_hi[NHEAD * HDIM * SEQ];  // [h][d][s]
__device__ __align__(16) __nv_bfloat16 g_vt_lo[NHEAD * HDIM * SEQ];

// ------------------------- helpers -----------------------------------------
__device__ __forceinline__ uint32_t smem_u32(const void* p) {
    uint32_t a;
    asm("{ .reg .u64 t; cvta.to.shared.u64 t, %1; cvt.u32.u64 %0, t; }" : "=r"(a) : "l"(p));
    return a;
}
#define CP_ASYNC16(s, g) \
    asm volatile("cp.async.cg.shared.global [%0], [%1], 16;" :: "r"(s), "l"(g))
#define CP_COMMIT()  asm volatile("cp.async.commit_group;" ::: "memory")
#define CP_WAIT(n)   asm volatile("cp.async.wait_group %0;" :: "n"(n) : "memory")

__device__ __forceinline__ void mma16816(float* c, const uint32_t* a,
                                         uint32_t b0, uint32_t b1) {
    asm volatile(
        "mma.sync.aligned.m16n8k16.row.col.f32.bf16.bf16.f32 "
        "{%0,%1,%2,%3}, {%4,%5,%6,%7}, {%8,%9}, {%0,%1,%2,%3};"
        : "+f"(c[0]), "+f"(c[1]), "+f"(c[2]), "+f"(c[3])
        : "r"(a[0]), "r"(a[1]), "r"(a[2]), "r"(a[3]), "r"(b0), "r"(b1));
}
__device__ __forceinline__ float ex2f(float x) {
    float y;
    asm("ex2.approx.ftz.f32 %0, %1;" : "=f"(y) : "f"(x));
    return y;
}
__device__ __forceinline__ uint32_t pack_bf16_rn(float lo, float hi) {
    uint32_t r;
    asm("cvt.rn.bf16x2.f32 %0, %1, %2;" : "=r"(r) : "f"(hi), "f"(lo));
    return r;
}

// ------------------------- conversion kernels ------------------------------
__global__ __launch_bounds__(256) void convert_split_kernel(
    const float* __restrict__ in, __nv_bfloat16* __restrict__ hi,
    __nv_bfloat16* __restrict__ lo, int n4)
{
    int i = blockIdx.x * 256 + threadIdx.x;
    if (i >= n4) return;
    float4 v = ((const float4*)in)[i];
    float vv[4] = {v.x, v.y, v.z, v.w};
    ushort4 h, l;
    unsigned short* hp = (unsigned short*)&h;
    unsigned short* lp = (unsigned short*)&l;
    #pragma unroll
    for (int j = 0; j < 4; j++) {
        __nv_bfloat16 bh = __float2bfloat16(vv[j]);
        float rem = vv[j] - __bfloat162float(bh);
        __nv_bfloat16 bl = __float2bfloat16(rem);
        hp[j] = *(unsigned short*)&bh;
        lp[j] = *(unsigned short*)&bl;
    }
    ((ushort4*)hi)[i] = h;
    ((ushort4*)lo)[i] = l;
}

// W[K][N] fp32 -> hi/lo [N][K] bf16 (transpose + split)
__global__ __launch_bounds__(256) void convert_transpose_kernel(
    const float* __restrict__ W, __nv_bfloat16* __restrict__ hi,
    __nv_bfloat16* __restrict__ lo, int K, int N)
{
    __shared__ float t[32][33];
    const int bn = blockIdx.x * 32, bk = blockIdx.y * 32;
    const int tx = threadIdx.x & 31, ty = threadIdx.x >> 5;
    #pragma unroll
    for (int r = 0; r < 32; r += 8)
        t[r + ty][tx] = W[(size_t)(bk + r + ty) * N + bn + tx];
    __syncthreads();
    #pragma unroll
    for (int r = 0; r < 32; r += 8) {
        float v = t[tx][r + ty];
        __nv_bfloat16 bh = __float2bfloat16(v);
        float rem = v - __bfloat162float(bh);
        __nv_bfloat16 bl = __float2bfloat16(rem);
        size_t o = (size_t)(bn + r + ty) * K + bk + tx;
        hi[o] = bh;
        lo[o] = bl;
    }
}

// split Q,K parts of g_qkv (parts 0,1) into bf16 hi/lo, same layout
__global__ __launch_bounds__(256) void split_qk_kernel()
{
    const int i = blockIdx.x * 256 + threadIdx.x;  // float4 index
    const int n4 = 2 * NHEAD * SEQ * HDIM / 4;
    if (i >= n4) return;
    const int elem = i * 4;
    const int part = elem >> 22;                   // 4M elems per part
    const int idx = elem & ((NHEAD * SEQ * HDIM) - 1);
    float4 v = *(const float4*)&g_qkv[elem];
    float vv[4] = {v.x, v.y, v.z, v.w};
    ushort4 h, l;
    unsigned short* hp = (unsigned short*)&h;
    unsigned short* lp = (unsigned short*)&l;
    #pragma unroll
    for (int j = 0; j < 4; j++) {
        __nv_bfloat16 bh = __float2bfloat16(vv[j]);
        float rem = vv[j] - __bfloat162float(bh);
        __nv_bfloat16 bl = __float2bfloat16(rem);
        hp[j] = *(unsigned short*)&bh;
        lp[j] = *(unsigned short*)&bl;
    }
    __nv_bfloat16* dh = part ? g_k_hi : g_q_hi;
    __nv_bfloat16* dl = part ? g_k_lo : g_q_lo;
    *(ushort4*)&dh[idx] = h;
    *(ushort4*)&dl[idx] = l;
}

// transpose V (part 2 of g_qkv) per head: [s][d] -> [d][s], split hi/lo
__global__ __launch_bounds__(256) void transpose_v_kernel()
{
    __shared__ float t[32][33];
    const int s0 = blockIdx.x * 32;
    const int d0 = blockIdx.y * 32;
    const int h = blockIdx.z;
    const float* V = g_qkv + (size_t)(2 * NHEAD + h) * SEQ * HDIM;
    const int tx = threadIdx.x & 31, ty = threadIdx.x >> 5;
    #pragma unroll
    for (int r = 0; r < 32; r += 8)
        t[r + ty][tx] = V[(size_t)(s0 + r + ty) * HDIM + d0 + tx];
    __syncthreads();
    #pragma unroll
    for (int r = 0; r < 32; r += 8) {
        float v = t[tx][r + ty];
        __nv_bfloat16 bh = __float2bfloat16(v);
        float rem = v - __bfloat162float(bh);
        __nv_bfloat16 bl = __float2bfloat16(rem);
        size_t o = ((size_t)h * HDIM + d0 + r + ty) * SEQ + s0 + tx;
        g_vt_hi[o] = bh;
        g_vt_lo[o] = bl;
    }
}

// ------------------------- mma.sync GEMM (unchanged from R3) ----------------
#define GK       DMODEL
#define KITERS   (GK / 32)
#define MAT_B    (128 * 40 * 2)
#define STAGE_B  (4 * MAT_B)
#define DYN_SMEM (2 * STAGE_B)

template <bool QKV>
__global__ __launch_bounds__(256, 1) void mma_gemm_kernel(
    const __nv_bfloat16* __restrict__ Ahi, const __nv_bfloat16* __restrict__ Alo,
    const __nv_bfloat16* __restrict__ Bhi, const __nv_bfloat16* __restrict__ Blo,
    const float* __restrict__ bias, float* __restrict__ out, int N)
{
    extern __shared__ char sm[];
    const uint32_t sb = smem_u32(sm);

    const int tid  = threadIdx.x;
    const int lane = tid & 31;
    const int wid  = tid >> 5;
    const int gid  = lane >> 2;
    const int tig  = lane & 3;
    const int wm   = wid & 3;
    const int wn   = wid >> 2;

    const int bm = blockIdx.y * 128;
    const int bn = blockIdx.x * 128;

    auto issue_stage = [&](int stage, int kt) {
        const uint32_t stb = sb + stage * STAGE_B;
        #pragma unroll
        for (int mat = 0; mat < 4; mat++) {
            const __nv_bfloat16* base =
                (mat == 0) ? Ahi : (mat == 1) ? Alo : (mat == 2) ? Bhi : Blo;
            const int r0 = (mat < 2) ? bm : bn;
            #pragma unroll
            for (int p = 0; p < 2; p++) {
                const int idx = p * 256 + tid;
                const int row = idx >> 2;
                const int c   = idx & 3;
                const char* g = (const char*)(base + (size_t)(r0 + row) * GK
                                              + kt * 32 + c * 8);
                CP_ASYNC16(stb + mat * MAT_B + row * 80 + c * 16, g);
            }
        }
    };

    float acc[2][8][4] = {};

    issue_stage(0, 0);
    CP_COMMIT();

    for (int kt = 0; kt < KITERS; kt++) {
        if (kt + 1 < KITERS) {
            issue_stage((kt + 1) & 1, kt + 1);
            CP_COMMIT();
            CP_WAIT(1);
        } else {
            CP_WAIT(0);
        }
        __syncthreads();

        const char* stg = sm + (kt & 1) * STAGE_B;
        const char* sAh = stg;
        const char* sAl = stg + MAT_B;
        const char* sBh = stg + 2 * MAT_B;
        const char* sBl = stg + 3 * MAT_B;

        #pragma unroll
        for (int ks = 0; ks < 2; ks++) {
            const int colb = (ks * 16 + tig * 2) * 2;

            uint32_t ah[2][4], al[2][4];
            #pragma unroll
            for (int mt = 0; mt < 2; mt++) {
                const int row = wm * 32 + mt * 16 + gid;
                ah[mt][0] = *(const uint32_t*)(sAh + row * 80 + colb);
                ah[mt][1] = *(const uint32_t*)(sAh + (row + 8) * 80 + colb);
                ah[mt][2] = *(const uint32_t*)(sAh + row * 80 + colb + 16);
                ah[mt][3] = *(const uint32_t*)(sAh + (row + 8) * 80 + colb + 16);
                al[mt][0] = *(const uint32_t*)(sAl + row * 80 + colb);
                al[mt][1] = *(const uint32_t*)(sAl + (row + 8) * 80 + colb);
                al[mt][2] = *(const uint32_t*)(sAl + row * 80 + colb + 16);
                al[mt][3] = *(const uint32_t*)(sAl + (row + 8) * 80 + colb + 16);
            }
            #pragma unroll
            for (int nt = 0; nt < 8; nt++) {
                const int nrow = wn * 64 + nt * 8 + gid;
                const uint32_t bh0 = *(const uint32_t*)(sBh + nrow * 80 + colb);
                const uint32_t bh1 = *(const uint32_t*)(sBh + nrow * 80 + colb + 16);
                const uint32_t bl0 = *(const uint32_t*)(sBl + nrow * 80 + colb);
                const uint32_t bl1 = *(const uint32_t*)(sBl + nrow * 80 + colb + 16);
                #pragma unroll
                for (int mt = 0; mt < 2; mt++) {
                    mma16816(acc[mt][nt], ah[mt], bh0, bh1);
                    mma16816(acc[mt][nt], ah[mt], bl0, bl1);
                    mma16816(acc[mt][nt], al[mt], bh0, bh1);
                }
            }
        }
        __syncthreads();
    }

    #pragma unroll
    for (int mt = 0; mt < 2; mt++) {
        const int r = bm + wm * 32 + mt * 16 + gid;
        #pragma unroll
        for (int nt = 0; nt < 8; nt++) {
            const int col = bn + wn * 64 + nt * 8 + tig * 2;
            const float2 bv = *(const float2*)&bias[col];
            float2 d0, d1;
            d0.x = acc[mt][nt][0] + bv.x;
            d0.y = acc[mt][nt][1] + bv.y;
            d1.x = acc[mt][nt][2] + bv.x;
            d1.y = acc[mt][nt][3] + bv.y;
            if (QKV) {
                const int part = col >> 10;
                const int h = (col >> 6) & 15;
                const int d = col & 63;
                float* dst = g_qkv + (((size_t)(part * NHEAD + h) * SEQ + r) << 6) + d;
                *(float2*)dst = d0;
                *(float2*)(dst + 8 * 64) = d1;
            } else {
                float* dst = out + (size_t)r * N + col;
                *(float2*)dst = d0;
                *(float2*)(dst + 8 * (size_t)N) = d1;
            }
        }
    }
}

// ---------------------------------------------------------------------------
// Flash attention on mma.sync. CTA: 128 q-rows x 1 head, 8 warps (16 rows ea).
// K-tiles of 64. smem stage = {Khi,Klo,Vthi,Vtlo}[64][72] halves (144B rows).
// ---------------------------------------------------------------------------
#define AT_MAT_B   9216                 // 64 * 144
#define AT_STAGE_B (4 * AT_MAT_B)       // 36864
#define AT_SMEM    (2 * AT_STAGE_B)     // 73728

__global__ __launch_bounds__(256, 1) void attn_mma_kernel()
{
    extern __shared__ char sm[];
    const uint32_t sb = smem_u32(sm);

    const int tid  = threadIdx.x;
    const int lane = tid & 31;
    const int w    = tid >> 5;
    const int gid  = lane >> 2;
    const int tig  = lane & 3;

    const int qt = 31 - blockIdx.x;  // long tiles first
    const int h  = blockIdx.y;
    const int q0 = qt * 128;
    const int wq0 = q0 + w * 16;

    // ---- stage Q (hi at sb, lo at sb+18432), rows [128][144B]
    {
        const __nv_bfloat16* Qh = g_q_hi + ((size_t)h * SEQ + q0) * HDIM;
        const __nv_bfloat16* Ql = g_q_lo + ((size_t)h * SEQ + q0) * HDIM;
        #pragma unroll
        for (int t = 0; t < 8; t++) {
            const int mat = t >> 2;                  // 0: hi, 1: lo
            const int within = (t & 3) * 256 + tid;  // 0..1023
            const int row = within >> 3;
            const int ch = within & 7;
            const __nv_bfloat16* src = (mat ? Ql : Qh) + (size_t)row * HDIM + ch * 8;
            CP_ASYNC16(sb + mat * 18432 + row * 144 + ch * 16, src);
        }
        CP_COMMIT();
        CP_WAIT(0);
        __syncthreads();
    }

    // ---- Q fragments (register resident)
    uint32_t qh[4][4], ql[4][4];
    {
        const char* q0p = sm + (w * 16 + gid) * 144 + tig * 4;
        #pragma unroll
        for (int ki = 0; ki < 4; ki++) {
            qh[ki][0] = *(const uint32_t*)(q0p + ki * 32);
            qh[ki][1] = *(const uint32_t*)(q0p + 8 * 144 + ki * 32);
            qh[ki][2] = *(const uint32_t*)(q0p + ki * 32 + 16);
            qh[ki][3] = *(const uint32_t*)(q0p + 8 * 144 + ki * 32 + 16);
            ql[ki][0] = *(const uint32_t*)(q0p + 18432 + ki * 32);
            ql[ki][1] = *(const uint32_t*)(q0p + 18432 + 8 * 144 + ki * 32);
            ql[ki][2] = *(const uint32_t*)(q0p + 18432 + ki * 32 + 16);
            ql[ki][3] = *(const uint32_t*)(q0p + 18432 + 8 * 144 + ki * 32 + 16);
        }
    }
    __syncthreads();  // Q reads done before K/V overwrite stage 0

    // ---- K/V stage loader
    auto load_kv = [&](int stage, int kt) {
        const uint32_t stb = sb + stage * AT_STAGE_B;
        #pragma unroll
        for (int t = 0; t < 8; t++) {
            const int mat = t >> 1;                  // 0 Khi, 1 Klo, 2 Vthi, 3 Vtlo
            const int within = (t & 1) * 256 + tid;  // 0..511
            const int row = within >> 3;
            const int ch = within & 7;
            const __nv_bfloat16* src;
            if (mat == 0)
                src = g_k_hi + ((size_t)h * SEQ + kt * 64 + row) * HDIM + ch * 8;
            else if (mat == 1)
                src = g_k_lo + ((size_t)h * SEQ + kt * 64 + row) * HDIM + ch * 8;
            else if (mat == 2)
                src = g_vt_hi + ((size_t)h * HDIM + row) * SEQ + kt * 64 + ch * 8;
            else
                src = g_vt_lo + ((size_t)h * HDIM + row) * SEQ + kt * 64 + ch * 8;
            CP_ASYNC16(stb + mat * AT_MAT_B + row * 144 + ch * 16, src);
        }
    };

    float o[8][4] = {};
    float m0 = -1e30f, m1 = -1e30f, l0 = 0.0f, l1 = 0.0f;
    const float SC = 0.1803368801111244f;  // 0.125 * log2(e)
    const int ktmax = 2 * qt + 1;

    load_kv(0, 0);
    CP_COMMIT();

    for (int kt = 0; kt <= ktmax; kt++) {
        if (kt < ktmax) {
            load_kv((kt + 1) & 1, kt + 1);
            CP_COMMIT();
            CP_WAIT(1);
        } else {
            CP_WAIT(0);
        }
        __syncthreads();

        const int kc0 = kt * 64;
        if (kc0 <= wq0 + 15) {  // not fully masked for this warp
            const char* stg = sm + (kt & 1) * AT_STAGE_B;
            const char* sKh = stg;
            const char* sKl = stg + AT_MAT_B;
            const char* sVh = stg + 2 * AT_MAT_B;
            const char* sVl = stg + 3 * AT_MAT_B;

            // S = Q K^T (3-MMA split)
            float s[8][4] = {};
            #pragma unroll
            for (int nt = 0; nt < 8; nt++) {
                const char* kb = sKh + (nt * 8 + gid) * 144 + tig * 4;
                const char* kb2 = sKl + (nt * 8 + gid) * 144 + tig * 4;
                #pragma unroll
                for (int ki = 0; ki < 4; ki++) {
                    const uint32_t bh0 = *(const uint32_t*)(kb + ki * 32);
                    const uint32_t bh1 = *(const uint32_t*)(kb + ki * 32 + 16);
                    const uint32_t bl0 = *(const uint32_t*)(kb2 + ki * 32);
                    const uint32_t bl1 = *(const uint32_t*)(kb2 + ki * 32 + 16);
                    mma16816(s[nt], qh[ki], bh0, bh1);
                    mma16816(s[nt], qh[ki], bl0, bl1);
                    mma16816(s[nt], ql[ki], bh0, bh1);
                }
            }

            // scale + causal mask
            const bool partial = (kc0 + 63) > wq0;
            const int r0 = wq0 + gid, r1 = r0 + 8;
            #pragma unroll
            for (int nt = 0; nt < 8; nt++) {
                const int cb = kc0 + nt * 8 + tig * 2;
                s[nt][0] *= SC; s[nt][1] *= SC; s[nt][2] *= SC; s[nt][3] *= SC;
                if (partial) {
                    if (cb > r0)     s[nt][0] = -1e30f;
                    if (cb + 1 > r0) s[nt][1] = -1e30f;
                    if (cb > r1)     s[nt][2] = -1e30f;
                    if (cb + 1 > r1) s[nt][3] = -1e30f;
                }
            }

            // row max (quad butterfly)
            float mx0 = -1e30f, mx1 = -1e30f;
            #pragma unroll
            for (int nt = 0; nt < 8; nt++) {
                mx0 = fmaxf(mx0, fmaxf(s[nt][0], s[nt][1]));
                mx1 = fmaxf(mx1, fmaxf(s[nt][2], s[nt][3]));
            }
            mx0 = fmaxf(mx0, __shfl_xor_sync(0xffffffffu, mx0, 1));
            mx0 = fmaxf(mx0, __shfl_xor_sync(0xffffffffu, mx0, 2));
            mx1 = fmaxf(mx1, __shfl_xor_sync(0xffffffffu, mx1, 1));
            mx1 = fmaxf(mx1, __shfl_xor_sync(0xffffffffu, mx1, 2));

            const float nm0 = fmaxf(m0, mx0);
            const float nm1 = fmaxf(m1, mx1);
            const float f0 = ex2f(m0 - nm0);
            const float f1 = ex2f(m1 - nm1);
            m0 = nm0; m1 = nm1;

            // p = exp2(s - m), pack hi (trunc) + lo (rn residual)
            uint32_t pah[4][4], pal[4][4];
            float rs0 = 0.0f, rs1 = 0.0f;
            #pragma unroll
            for (int j = 0; j < 4; j++) {
                #pragma unroll
                for (int half = 0; half < 2; half++) {
                    const int nt = 2 * j + half;
                    float p0 = ex2f(s[nt][0] - nm0);
                    float p1 = ex2f(s[nt][1] - nm0);
                    float p2 = ex2f(s[nt][2] - nm1);
                    float p3 = ex2f(s[nt][3] - nm1);
                    rs0 += p0 + p1;
                    rs1 += p2 + p3;
                    uint32_t u0 = __float_as_uint(p0), u1 = __float_as_uint(p1);
                    uint32_t u2 = __float_as_uint(p2), u3 = __float_as_uint(p3);
                    float h0 = __uint_as_float(u0 & 0xffff0000u);
                    float h1 = __uint_as_float(u1 & 0xffff0000u);
                    float h2 = __uint_as_float(u2 & 0xffff0000u);
                    float h3 = __uint_as_float(u3 & 0xffff0000u);
                    pah[j][0 + 2 * half] = __byte_perm(u0, u1, 0x7632);
                    pah[j][1 + 2 * half] = __byte_perm(u2, u3, 0x7632);
                    pal[j][0 + 2 * half] = pack_bf16_rn(p0 - h0, p1 - h1);
                    pal[j][1 + 2 * half] = pack_bf16_rn(p2 - h2, p3 - h3);
                }
            }
            rs0 += __shfl_xor_sync(0xffffffffu, rs0, 1);
            rs0 += __shfl_xor_sync(0xffffffffu, rs0, 2);
            rs1 += __shfl_xor_sync(0xffffffffu, rs1, 1);
            rs1 += __shfl_xor_sync(0xffffffffu, rs1, 2);
            l0 = l0 * f0 + rs0;
            l1 = l1 * f1 + rs1;

            // rescale O, then O += P V (3-MMA split)
            #pragma unroll
            for (int nt = 0; nt < 8; nt++) {
                o[nt][0] *= f0; o[nt][1] *= f0;
                o[nt][2] *= f1; o[nt][3] *= f1;
            }
            #pragma unroll
            for (int nt = 0; nt < 8; nt++) {
                const char* vb = sVh + (nt * 8 + gid) * 144 + tig * 4;
                const char* vb2 = sVl + (nt * 8 + gid) * 144 + tig * 4;
                #pragma unroll
                for (int j = 0; j < 4; j++) {
                    const uint32_t bh0 = *(const uint32_t*)(vb + j * 32);
                    const uint32_t bh1 = *(const uint32_t*)(vb + j * 32 + 16);
                    const uint32_t bl0 = *(const uint32_t*)(vb2 + j * 32);
                    const uint32_t bl1 = *(const uint32_t*)(vb2 + j * 32 + 16);
                    mma16816(o[nt], pah[j], bh0, bh1);
                    mma16816(o[nt], pal[j], bh0, bh1);
                    mma16816(o[nt], pah[j], bl0, bl1);
                }
            }
        }
        __syncthreads();
    }

    // ---- epilogue: O/l -> g_att hi/lo [s][dmodel]
    const float inv0 = 1.0f / l0;
    const float inv1 = 1.0f / l1;
    #pragma unroll
    for (int nt = 0; nt < 8; nt++) {
        const int col = h * HDIM + nt * 8 + tig * 2;
        {
            const float v0 = o[nt][0] * inv0, v1 = o[nt][1] * inv0;
            const uint32_t u0 = __float_as_uint(v0), u1 = __float_as_uint(v1);
            const float h0 = __uint_as_float(u0 & 0xffff0000u);
            const float h1 = __uint_as_float(u1 & 0xffff0000u);
            const size_t off = (size_t)(wq0 + gid) * DMODEL + col;
            *(uint32_t*)&g_att_hi[off] = __byte_perm(u0, u1, 0x7632);
            *(uint32_t*)&g_att_lo[off] = pack_bf16_rn(v0 - h0, v1 - h1);
        }
        {
            const float v0 = o[nt][2] * inv1, v1 = o[nt][3] * inv1;
            const uint32_t u0 = __float_as_uint(v0), u1 = __float_as_uint(v1);
            const float h0 = __uint_as_float(u0 & 0xffff0000u);
            const float h1 = __uint_as_float(u1 & 0xffff0000u);
            const size_t off = (size_t)(wq0 + gid + 8) * DMODEL + col;
            *(uint32_t*)&g_att_hi[off] = __byte_perm(u0, u1, 0x7632);
            *(uint32_t*)&g_att_lo[off] = pack_bf16_rn(v0 - h0, v1 - h1);
        }
    }
}

// ---------------------------------------------------------------------------
extern "C" void kernel_launch(void* const* d_in, const int* in_sizes, int n_in,
                              void* d_out, int out_size)
{
    const float* x     = (const float*)d_in[0];
    const float* Wqkv  = (const float*)d_in[1];
    const float* bqkv  = (const float*)d_in[2];
    const float* Wproj = (const float*)d_in[3];
    const float* bproj = (const float*)d_in[4];
    float* out = (float*)d_out;

    static bool attr_done = false;
    if (!attr_done) {
        cudaFuncSetAttribute(mma_gemm_kernel<true>,
                             cudaFuncAttributeMaxDynamicSharedMemorySize, DYN_SMEM);
        cudaFuncSetAttribute(mma_gemm_kernel<false>,
                             cudaFuncAttributeMaxDynamicSharedMemorySize, DYN_SMEM);
        cudaFuncSetAttribute(attn_mma_kernel,
                             cudaFuncAttributeMaxDynamicSharedMemorySize, AT_SMEM);
        attr_done = true;
    }

    __nv_bfloat16 *xhi, *xlo, *wqh, *wql, *wph, *wpl, *ahi, *alo;
    cudaGetSymbolAddress((void**)&xhi, g_xhi);
    cudaGetSymbolAddress((void**)&xlo, g_xlo);
    cudaGetSymbolAddress((void**)&wqh, g_wqkvT_hi);
    cudaGetSymbolAddress((void**)&wql, g_wqkvT_lo);
    cudaGetSymbolAddress((void**)&wph, g_wprojT_hi);
    cudaGetSymbolAddress((void**)&wpl, g_wprojT_lo);
    cudaGetSymbolAddress((void**)&ahi, g_att_hi);
    cudaGetSymbolAddress((void**)&alo, g_att_lo);

    // 1) input conversions
    convert_split_kernel<<<(SEQ * DMODEL / 4 + 255) / 256, 256>>>(x, xhi, xlo,
                                                                  SEQ * DMODEL / 4);
    convert_transpose_kernel<<<dim3(N_QKV / 32, DMODEL / 32), 256>>>(Wqkv, wqh, wql,
                                                                     DMODEL, N_QKV);
    convert_transpose_kernel<<<dim3(DMODEL / 32, DMODEL / 32), 256>>>(Wproj, wph, wpl,
                                                                      DMODEL, DMODEL);
    // 2) GEMM1: qkv = x @ Wqkv + bqkv -> g_qkv (permuted fp32)
    mma_gemm_kernel<true><<<dim3(N_QKV / 128, SEQ / 128), 256, DYN_SMEM>>>(
        xhi, xlo, wqh, wql, bqkv, nullptr, N_QKV);
    // 3) prep attention operands (split + V transpose)
    split_qk_kernel<<<(2 * NHEAD * SEQ * HDIM / 4 + 255) / 256, 256>>>();
    transpose_v_kernel<<<dim3(SEQ / 32, HDIM / 32, NHEAD), 256>>>();
    // 4) attention (mma.sync) -> g_att_hi/lo
    attn_mma_kernel<<<dim3(SEQ / 128, NHEAD), 256, AT_SMEM>>>();
    // 5) GEMM2: out = att @ Wproj + bproj
    mma_gemm_kernel<false><<<dim3(DMODEL / 128, SEQ / 128), 256, DYN_SMEM>>>(
        ahi, alo, wph, wpl, bproj, out, DMODEL);
}

// round 5
// speedup vs baseline: 3.2335x; 1.0434x over previous
#include <cuda_runtime.h>
#include <cuda_bf16.h>
#include <cstdint>

// ---------------------------------------------------------------------------
// Attention_32186484917066 — R5: ldmatrix fragments + 3-stage cp.async
// pipelines + 1 barrier/iter in all MMA kernels; GEMM1 epilogue fuses QK split.
// ---------------------------------------------------------------------------

#define SEQ    4096
#define DMODEL 1024
#define NHEAD  16
#define HDIM   64
#define N_QKV  3072

// ------------------------- device scratch (no allocs) -----------------------
__device__ __align__(16) __nv_bfloat16 g_xhi[SEQ * DMODEL];
__device__ __align__(16) __nv_bfloat16 g_xlo[SEQ * DMODEL];
__device__ __align__(16) __nv_bfloat16 g_wqkvT_hi[N_QKV * DMODEL];   // [N][K]
__device__ __align__(16) __nv_bfloat16 g_wqkvT_lo[N_QKV * DMODEL];
__device__ __align__(16) __nv_bfloat16 g_wprojT_hi[DMODEL * DMODEL]; // [N][K]
__device__ __align__(16) __nv_bfloat16 g_wprojT_lo[DMODEL * DMODEL];
__device__ float g_qkv[3 * NHEAD * SEQ * HDIM];  // V region (part 2) used fp32
__device__ __align__(16) __nv_bfloat16 g_att_hi[SEQ * DMODEL];
__device__ __align__(16) __nv_bfloat16 g_att_lo[SEQ * DMODEL];
__device__ __align__(16) __nv_bfloat16 g_q_hi[NHEAD * SEQ * HDIM];   // [h][s][d]
__device__ __align__(16) __nv_bfloat16 g_q_lo[NHEAD * SEQ * HDIM];
__device__ __align__(16) __nv_bfloat16 g_k_hi[NHEAD * SEQ * HDIM];   // [h][s][d]
__device__ __align__(16) __nv_bfloat16 g_k_lo[NHEAD * SEQ * HDIM];
__device__ __align__(16) __nv_bfloat16 g_vt_hi[NHEAD * HDIM * SEQ];  // [h][d][s]
__device__ __align__(16) __nv_bfloat16 g_vt_lo[NHEAD * HDIM * SEQ];

// ------------------------- helpers -----------------------------------------
__device__ __forceinline__ uint32_t smem_u32(const void* p) {
    uint32_t a;
    asm("{ .reg .u64 t; cvta.to.shared.u64 t, %1; cvt.u32.u64 %0, t; }" : "=r"(a) : "l"(p));
    return a;
}
#define CP_ASYNC16(s, g) \
    asm volatile("cp.async.cg.shared.global [%0], [%1], 16;" :: "r"(s), "l"(g))
#define CP_COMMIT()  asm volatile("cp.async.commit_group;" ::: "memory")
#define CP_WAIT(n)   asm volatile("cp.async.wait_group %0;" :: "n"(n) : "memory")

__device__ __forceinline__ void mma16816(float* c, const uint32_t* a,
                                         uint32_t b0, uint32_t b1) {
    asm volatile(
        "mma.sync.aligned.m16n8k16.row.col.f32.bf16.bf16.f32 "
        "{%0,%1,%2,%3}, {%4,%5,%6,%7}, {%8,%9}, {%0,%1,%2,%3};"
        : "+f"(c[0]), "+f"(c[1]), "+f"(c[2]), "+f"(c[3])
        : "r"(a[0]), "r"(a[1]), "r"(a[2]), "r"(a[3]), "r"(b0), "r"(b1));
}
__device__ __forceinline__ void ldm_x4(uint32_t* r, uint32_t addr) {
    asm volatile("ldmatrix.sync.aligned.m8n8.x4.shared.b16 {%0,%1,%2,%3}, [%4];"
                 : "=r"(r[0]), "=r"(r[1]), "=r"(r[2]), "=r"(r[3]) : "r"(addr));
}
__device__ __forceinline__ float ex2f(float x) {
    float y;
    asm("ex2.approx.ftz.f32 %0, %1;" : "=f"(y) : "f"(x));
    return y;
}
__device__ __forceinline__ uint32_t pack_bf16_rn(float lo, float hi) {
    uint32_t r;
    asm("cvt.rn.bf16x2.f32 %0, %1, %2;" : "=r"(r) : "f"(hi), "f"(lo));
    return r;
}
__device__ __forceinline__ void split2(float2 v, uint32_t& hi, uint32_t& lo) {
    const uint32_t ux = __float_as_uint(v.x), uy = __float_as_uint(v.y);
    const float hx = __uint_as_float(ux & 0xffff0000u);
    const float hy = __uint_as_float(uy & 0xffff0000u);
    hi = __byte_perm(ux, uy, 0x7632);
    lo = pack_bf16_rn(v.x - hx, v.y - hy);
}

// ------------------------- conversion kernels ------------------------------
__global__ __launch_bounds__(256) void convert_split_kernel(
    const float* __restrict__ in, __nv_bfloat16* __restrict__ hi,
    __nv_bfloat16* __restrict__ lo, int n4)
{
    int i = blockIdx.x * 256 + threadIdx.x;
    if (i >= n4) return;
    float4 v = ((const float4*)in)[i];
    float vv[4] = {v.x, v.y, v.z, v.w};
    ushort4 h, l;
    unsigned short* hp = (unsigned short*)&h;
    unsigned short* lp = (unsigned short*)&l;
    #pragma unroll
    for (int j = 0; j < 4; j++) {
        __nv_bfloat16 bh = __float2bfloat16(vv[j]);
        float rem = vv[j] - __bfloat162float(bh);
        __nv_bfloat16 bl = __float2bfloat16(rem);
        hp[j] = *(unsigned short*)&bh;
        lp[j] = *(unsigned short*)&bl;
    }
    ((ushort4*)hi)[i] = h;
    ((ushort4*)lo)[i] = l;
}

// W[K][N] fp32 -> hi/lo [N][K] bf16 (transpose + split)
__global__ __launch_bounds__(256) void convert_transpose_kernel(
    const float* __restrict__ W, __nv_bfloat16* __restrict__ hi,
    __nv_bfloat16* __restrict__ lo, int K, int N)
{
    __shared__ float t[32][33];
    const int bn = blockIdx.x * 32, bk = blockIdx.y * 32;
    const int tx = threadIdx.x & 31, ty = threadIdx.x >> 5;
    #pragma unroll
    for (int r = 0; r < 32; r += 8)
        t[r + ty][tx] = W[(size_t)(bk + r + ty) * N + bn + tx];
    __syncthreads();
    #pragma unroll
    for (int r = 0; r < 32; r += 8) {
        float v = t[tx][r + ty];
        __nv_bfloat16 bh = __float2bfloat16(v);
        float rem = v - __bfloat162float(bh);
        __nv_bfloat16 bl = __float2bfloat16(rem);
        size_t o = (size_t)(bn + r + ty) * K + bk + tx;
        hi[o] = bh;
        lo[o] = bl;
    }
}

// transpose V (part 2 of g_qkv) per head: [s][d] -> [d][s], split hi/lo
__global__ __launch_bounds__(256) void transpose_v_kernel()
{
    __shared__ float t[32][33];
    const int s0 = blockIdx.x * 32;
    const int d0 = blockIdx.y * 32;
    const int h = blockIdx.z;
    const float* V = g_qkv + (size_t)(2 * NHEAD + h) * SEQ * HDIM;
    const int tx = threadIdx.x & 31, ty = threadIdx.x >> 5;
    #pragma unroll
    for (int r = 0; r < 32; r += 8)
        t[r + ty][tx] = V[(size_t)(s0 + r + ty) * HDIM + d0 + tx];
    __syncthreads();
    #pragma unroll
    for (int r = 0; r < 32; r += 8) {
        float v = t[tx][r + ty];
        __nv_bfloat16 bh = __float2bfloat16(v);
        float rem = v - __bfloat162float(bh);
        __nv_bfloat16 bl = __float2bfloat16(rem);
        size_t o = ((size_t)h * HDIM + d0 + r + ty) * SEQ + s0 + tx;
        g_vt_hi[o] = bh;
        g_vt_lo[o] = bl;
    }
}

// ------------------------- mma.sync GEMM ------------------------------------
// CTA 128x128, BK=32, 8 warps (32x64 warp tile), 3-stage cp.async, ldmatrix.
#define GK       DMODEL
#define KITERS   (GK / 32)
#define MAT_B    (128 * 40 * 2)     // 10240, rows padded to 80B
#define STAGE_B  (4 * MAT_B)        // 40960
#define DYN_SMEM (3 * STAGE_B)      // 122880

template <bool QKV>
__global__ __launch_bounds__(256, 1) void mma_gemm_kernel(
    const __nv_bfloat16* __restrict__ Ahi, const __nv_bfloat16* __restrict__ Alo,
    const __nv_bfloat16* __restrict__ Bhi, const __nv_bfloat16* __restrict__ Blo,
    const float* __restrict__ bias, float* __restrict__ out, int N)
{
    extern __shared__ char sm[];
    const uint32_t sb = smem_u32(sm);

    const int tid  = threadIdx.x;
    const int lane = tid & 31;
    const int wid  = tid >> 5;
    const int gid  = lane >> 2;
    const int tig  = lane & 3;
    const int wm   = wid & 3;
    const int wn   = wid >> 2;

    const int bm = blockIdx.y * 128;
    const int bn = blockIdx.x * 128;

    // ldmatrix per-lane offsets
    const uint32_t aoff = (lane & 15) * 80 + (lane >> 4) * 16;
    const uint32_t boff = ((lane & 7) + (lane >> 4) * 8) * 80 + ((lane >> 3) & 1) * 16;

    auto issue_stage = [&](int stage, int kt) {
        const uint32_t stb = sb + stage * STAGE_B;
        #pragma unroll
        for (int mat = 0; mat < 4; mat++) {
            const __nv_bfloat16* base =
                (mat == 0) ? Ahi : (mat == 1) ? Alo : (mat == 2) ? Bhi : Blo;
            const int r0 = (mat < 2) ? bm : bn;
            #pragma unroll
            for (int p = 0; p < 2; p++) {
                const int idx = p * 256 + tid;
                const int row = idx >> 2;
                const int c   = idx & 3;
                const char* g = (const char*)(base + (size_t)(r0 + row) * GK
                                              + kt * 32 + c * 8);
                CP_ASYNC16(stb + mat * MAT_B + row * 80 + c * 16, g);
            }
        }
    };

    float acc[2][8][4] = {};

    issue_stage(0, 0);
    CP_COMMIT();
    issue_stage(1, 1);
    CP_COMMIT();

    for (int kt = 0; kt < KITERS; kt++) {
        if (kt + 1 < KITERS) { CP_WAIT(1); } else { CP_WAIT(0); }
        __syncthreads();
        if (kt + 2 < KITERS) {
            issue_stage((kt + 2) % 3, kt + 2);
            CP_COMMIT();
        }

        const uint32_t stg = sb + (kt % 3) * STAGE_B;
        const uint32_t bAh = stg;
        const uint32_t bAl = stg + MAT_B;
        const uint32_t bBh = stg + 2 * MAT_B;
        const uint32_t bBl = stg + 3 * MAT_B;

        #pragma unroll
        for (int ks = 0; ks < 2; ks++) {
            uint32_t ah[2][4], al[2][4];
            ldm_x4(ah[0], bAh + (wm * 32) * 80 + ks * 32 + aoff);
            ldm_x4(ah[1], bAh + (wm * 32 + 16) * 80 + ks * 32 + aoff);
            ldm_x4(al[0], bAl + (wm * 32) * 80 + ks * 32 + aoff);
            ldm_x4(al[1], bAl + (wm * 32 + 16) * 80 + ks * 32 + aoff);
            #pragma unroll
            for (int ntp = 0; ntp < 4; ntp++) {
                uint32_t bh[4], bl[4];
                ldm_x4(bh, bBh + (wn * 64 + ntp * 16) * 80 + ks * 32 + boff);
                ldm_x4(bl, bBl + (wn * 64 + ntp * 16) * 80 + ks * 32 + boff);
                #pragma unroll
                for (int mt = 0; mt < 2; mt++) {
                    mma16816(acc[mt][2 * ntp],     ah[mt], bh[0], bh[1]);
                    mma16816(acc[mt][2 * ntp],     ah[mt], bl[0], bl[1]);
                    mma16816(acc[mt][2 * ntp],     al[mt], bh[0], bh[1]);
                    mma16816(acc[mt][2 * ntp + 1], ah[mt], bh[2], bh[3]);
                    mma16816(acc[mt][2 * ntp + 1], ah[mt], bl[2], bl[3]);
                    mma16816(acc[mt][2 * ntp + 1], al[mt], bh[2], bh[3]);
                }
            }
        }
    }

    // epilogue
    #pragma unroll
    for (int mt = 0; mt < 2; mt++) {
        const int r = bm + wm * 32 + mt * 16 + gid;
        #pragma unroll
        for (int nt = 0; nt < 8; nt++) {
            const int col = bn + wn * 64 + nt * 8 + tig * 2;
            const float2 bv = *(const float2*)&bias[col];
            float2 d0, d1;
            d0.x = acc[mt][nt][0] + bv.x;
            d0.y = acc[mt][nt][1] + bv.y;
            d1.x = acc[mt][nt][2] + bv.x;
            d1.y = acc[mt][nt][3] + bv.y;
            if (QKV) {
                const int part = col >> 10;
                const int hh = (col >> 6) & 15;
                const int d = col & 63;
                if (part < 2) {
                    __nv_bfloat16* dh = part ? g_k_hi : g_q_hi;
                    __nv_bfloat16* dl = part ? g_k_lo : g_q_lo;
                    const size_t i0 = ((size_t)hh * SEQ + r) * HDIM + d;
                    uint32_t hi, lo;
                    split2(d0, hi, lo);
                    *(uint32_t*)&dh[i0] = hi;
                    *(uint32_t*)&dl[i0] = lo;
                    split2(d1, hi, lo);
                    *(uint32_t*)&dh[i0 + 8 * HDIM] = hi;
                    *(uint32_t*)&dl[i0 + 8 * HDIM] = lo;
                } else {
                    float* dst = g_qkv + (((size_t)(2 * NHEAD + hh) * SEQ + r) << 6) + d;
                    *(float2*)dst = d0;
                    *(float2*)(dst + 8 * 64) = d1;
                }
            } else {
                float* dst = out + (size_t)r * N + col;
                *(float2*)dst = d0;
                *(float2*)(dst + 8 * (size_t)N) = d1;
            }
        }
    }
}

// ---------------------------------------------------------------------------
// Flash attention on mma.sync + ldmatrix. CTA: 128 q-rows x head, 8 warps.
// 3-stage K/V ring (stages of {Khi,Klo,Vthi,Vtlo}[64][144B]) + Q region.
// ---------------------------------------------------------------------------
#define AT_MAT_B   9216                  // 64 * 144
#define AT_STAGE_B (4 * AT_MAT_B)        // 36864
#define AT_Q_B     (2 * 128 * 144)       // 36864
#define AT_SMEM    (3 * AT_STAGE_B + AT_Q_B)  // 147456

__global__ __launch_bounds__(256, 1) void attn_mma_kernel()
{
    extern __shared__ char sm[];
    const uint32_t sb = smem_u32(sm);
    const uint32_t qbase = sb + 3 * AT_STAGE_B;

    const int tid  = threadIdx.x;
    const int lane = tid & 31;
    const int w    = tid >> 5;
    const int gid  = lane >> 2;
    const int tig  = lane & 3;

    const int qt = 31 - blockIdx.x;
    const int h  = blockIdx.y;
    const int q0 = qt * 128;
    const int wq0 = q0 + w * 16;
    const int ktmax = 2 * qt + 1;

    const uint32_t boff = ((lane & 7) + (lane >> 4) * 8) * 144 + ((lane >> 3) & 1) * 16;

    auto load_kv = [&](int stage, int kt) {
        const uint32_t stb = sb + stage * AT_STAGE_B;
        #pragma unroll
        for (int t = 0; t < 8; t++) {
            const int mat = t >> 1;
            const int within = (t & 1) * 256 + tid;
            const int row = within >> 3;
            const int ch = within & 7;
            const __nv_bfloat16* src;
            if (mat == 0)
                src = g_k_hi + ((size_t)h * SEQ + kt * 64 + row) * HDIM + ch * 8;
            else if (mat == 1)
                src = g_k_lo + ((size_t)h * SEQ + kt * 64 + row) * HDIM + ch * 8;
            else if (mat == 2)
                src = g_vt_hi + ((size_t)h * HDIM + row) * SEQ + kt * 64 + ch * 8;
            else
                src = g_vt_lo + ((size_t)h * HDIM + row) * SEQ + kt * 64 + ch * 8;
            CP_ASYNC16(stb + mat * AT_MAT_B + row * 144 + ch * 16, src);
        }
    };

    // ---- prologue: Q into its own region, stages 0/1 of K/V
    {
        const __nv_bfloat16* Qh = g_q_hi + ((size_t)h * SEQ + q0) * HDIM;
        const __nv_bfloat16* Ql = g_q_lo + ((size_t)h * SEQ + q0) * HDIM;
        #pragma unroll
        for (int t = 0; t < 8; t++) {
            const int mat = t >> 2;
            const int within = (t & 3) * 256 + tid;
            const int row = within >> 3;
            const int ch = within & 7;
            const __nv_bfloat16* src = (mat ? Ql : Qh) + (size_t)row * HDIM + ch * 8;
            CP_ASYNC16(qbase + mat * 18432 + row * 144 + ch * 16, src);
        }
        CP_COMMIT();
    }
    load_kv(0, 0);
    CP_COMMIT();
    if (ktmax >= 1) { load_kv(1, 1); CP_COMMIT(); }

    // wait for Q (leave up to 2 K/V groups pending), read Q fragments
    if (ktmax >= 1) { CP_WAIT(2); } else { CP_WAIT(1); }
    __syncthreads();

    uint32_t qh[4][4], ql[4][4];
    {
        const uint32_t aoff = (lane & 15) * 144 + (lane >> 4) * 16;
        #pragma unroll
        for (int ki = 0; ki < 4; ki++) {
            ldm_x4(qh[ki], qbase + (w * 16) * 144 + ki * 32 + aoff);
            ldm_x4(ql[ki], qbase + 18432 + (w * 16) * 144 + ki * 32 + aoff);
        }
    }

    float o[8][4] = {};
    float m0 = -1e30f, m1 = -1e30f, l0 = 0.0f, l1 = 0.0f;
    const float SC = 0.1803368801111244f;  // 0.125 * log2(e)

    for (int kt = 0; kt <= ktmax; kt++) {
        if (kt + 1 <= ktmax) { CP_WAIT(1); } else { CP_WAIT(0); }
        __syncthreads();
        if (kt + 2 <= ktmax) {
            load_kv((kt + 2) % 3, kt + 2);
            CP_COMMIT();
        }

        const int kc0 = kt * 64;
        if (kc0 > wq0 + 15) continue;  // fully masked for this warp

        const uint32_t stg = sb + (kt % 3) * AT_STAGE_B;
        const uint32_t bKh = stg;
        const uint32_t bKl = stg + AT_MAT_B;
        const uint32_t bVh = stg + 2 * AT_MAT_B;
        const uint32_t bVl = stg + 3 * AT_MAT_B;

        // ---- S = Q K^T (3-MMA split)
        float s[8][4] = {};
        #pragma unroll
        for (int ntp = 0; ntp < 4; ntp++) {
            #pragma unroll
            for (int ki = 0; ki < 4; ki++) {
                uint32_t bh[4], bl[4];
                ldm_x4(bh, bKh + (ntp * 16) * 144 + ki * 32 + boff);
                ldm_x4(bl, bKl + (ntp * 16) * 144 + ki * 32 + boff);
                mma16816(s[2 * ntp],     qh[ki], bh[0], bh[1]);
                mma16816(s[2 * ntp],     qh[ki], bl[0], bl[1]);
                mma16816(s[2 * ntp],     ql[ki], bh[0], bh[1]);
                mma16816(s[2 * ntp + 1], qh[ki], bh[2], bh[3]);
                mma16816(s[2 * ntp + 1], qh[ki], bl[2], bl[3]);
                mma16816(s[2 * ntp + 1], ql[ki], bh[2], bh[3]);
            }
        }

        // scale + causal mask
        const bool partial = (kc0 + 63) > wq0;
        const int r0 = wq0 + gid, r1 = r0 + 8;
        #pragma unroll
        for (int nt = 0; nt < 8; nt++) {
            const int cb = kc0 + nt * 8 + tig * 2;
            s[nt][0] *= SC; s[nt][1] *= SC; s[nt][2] *= SC; s[nt][3] *= SC;
            if (partial) {
                if (cb > r0)     s[nt][0] = -1e30f;
                if (cb + 1 > r0) s[nt][1] = -1e30f;
                if (cb > r1)     s[nt][2] = -1e30f;
                if (cb + 1 > r1) s[nt][3] = -1e30f;
            }
        }

        // online softmax
        float mx0 = -1e30f, mx1 = -1e30f;
        #pragma unroll
        for (int nt = 0; nt < 8; nt++) {
            mx0 = fmaxf(mx0, fmaxf(s[nt][0], s[nt][1]));
            mx1 = fmaxf(mx1, fmaxf(s[nt][2], s[nt][3]));
        }
        mx0 = fmaxf(mx0, __shfl_xor_sync(0xffffffffu, mx0, 1));
        mx0 = fmaxf(mx0, __shfl_xor_sync(0xffffffffu, mx0, 2));
        mx1 = fmaxf(mx1, __shfl_xor_sync(0xffffffffu, mx1, 1));
        mx1 = fmaxf(mx1, __shfl_xor_sync(0xffffffffu, mx1, 2));

        const float nm0 = fmaxf(m0, mx0);
        const float nm1 = fmaxf(m1, mx1);
        const float f0 = ex2f(m0 - nm0);
        const float f1 = ex2f(m1 - nm1);
        m0 = nm0; m1 = nm1;

        uint32_t pah[4][4], pal[4][4];
        float rs0 = 0.0f, rs1 = 0.0f;
        #pragma unroll
        for (int j = 0; j < 4; j++) {
            #pragma unroll
            for (int half = 0; half < 2; half++) {
                const int nt = 2 * j + half;
                float p0 = ex2f(s[nt][0] - nm0);
                float p1 = ex2f(s[nt][1] - nm0);
                float p2 = ex2f(s[nt][2] - nm1);
                float p3 = ex2f(s[nt][3] - nm1);
                rs0 += p0 + p1;
                rs1 += p2 + p3;
                uint32_t u0 = __float_as_uint(p0), u1 = __float_as_uint(p1);
                uint32_t u2 = __float_as_uint(p2), u3 = __float_as_uint(p3);
                float h0 = __uint_as_float(u0 & 0xffff0000u);
                float h1 = __uint_as_float(u1 & 0xffff0000u);
                float h2 = __uint_as_float(u2 & 0xffff0000u);
                float h3 = __uint_as_float(u3 & 0xffff0000u);
                pah[j][0 + 2 * half] = __byte_perm(u0, u1, 0x7632);
                pah[j][1 + 2 * half] = __byte_perm(u2, u3, 0x7632);
                pal[j][0 + 2 * half] = pack_bf16_rn(p0 - h0, p1 - h1);
                pal[j][1 + 2 * half] = pack_bf16_rn(p2 - h2, p3 - h3);
            }
        }
        rs0 += __shfl_xor_sync(0xffffffffu, rs0, 1);
        rs0 += __shfl_xor_sync(0xffffffffu, rs0, 2);
        rs1 += __shfl_xor_sync(0xffffffffu, rs1, 1);
        rs1 += __shfl_xor_sync(0xffffffffu, rs1, 2);
        l0 = l0 * f0 + rs0;
        l1 = l1 * f1 + rs1;

        #pragma unroll
        for (int nt = 0; nt < 8; nt++) {
            o[nt][0] *= f0; o[nt][1] *= f0;
            o[nt][2] *= f1; o[nt][3] *= f1;
        }

        // ---- O += P V (3-MMA split)
        #pragma unroll
        for (int ntp = 0; ntp < 4; ntp++) {
            #pragma unroll
            for (int j = 0; j < 4; j++) {
                uint32_t bh[4], bl[4];
                ldm_x4(bh, bVh + (ntp * 16) * 144 + j * 32 + boff);
                ldm_x4(bl, bVl + (ntp * 16) * 144 + j * 32 + boff);
                mma16816(o[2 * ntp],     pah[j], bh[0], bh[1]);
                mma16816(o[2 * ntp],     pal[j], bh[0], bh[1]);
                mma16816(o[2 * ntp],     pah[j], bl[0], bl[1]);
                mma16816(o[2 * ntp + 1], pah[j], bh[2], bh[3]);
                mma16816(o[2 * ntp + 1], pal[j], bh[2], bh[3]);
                mma16816(o[2 * ntp + 1], pah[j], bl[2], bl[3]);
            }
        }
    }

    // ---- epilogue: O/l -> g_att hi/lo [s][dmodel]
    const float inv0 = 1.0f / l0;
    const float inv1 = 1.0f / l1;
    #pragma unroll
    for (int nt = 0; nt < 8; nt++) {
        const int col = h * HDIM + nt * 8 + tig * 2;
        {
            float2 v = make_float2(o[nt][0] * inv0, o[nt][1] * inv0);
            uint32_t hi, lo;
            split2(v, hi, lo);
            const size_t off = (size_t)(wq0 + gid) * DMODEL + col;
            *(uint32_t*)&g_att_hi[off] = hi;
            *(uint32_t*)&g_att_lo[off] = lo;
        }
        {
            float2 v = make_float2(o[nt][2] * inv1, o[nt][3] * inv1);
            uint32_t hi, lo;
            split2(v, hi, lo);
            const size_t off = (size_t)(wq0 + gid + 8) * DMODEL + col;
            *(uint32_t*)&g_att_hi[off] = hi;
            *(uint32_t*)&g_att_lo[off] = lo;
        }
    }
}

// ---------------------------------------------------------------------------
extern "C" void kernel_launch(void* const* d_in, const int* in_sizes, int n_in,
                              void* d_out, int out_size)
{
    const float* x     = (const float*)d_in[0];
    const float* Wqkv  = (const float*)d_in[1];
    const float* bqkv  = (const float*)d_in[2];
    const float* Wproj = (const float*)d_in[3];
    const float* bproj = (const float*)d_in[4];
    float* out = (float*)d_out;

    static bool attr_done = false;
    if (!attr_done) {
        cudaFuncSetAttribute(mma_gemm_kernel<true>,
                             cudaFuncAttributeMaxDynamicSharedMemorySize, DYN_SMEM);
        cudaFuncSetAttribute(mma_gemm_kernel<false>,
                             cudaFuncAttributeMaxDynamicSharedMemorySize, DYN_SMEM);
        cudaFuncSetAttribute(attn_mma_kernel,
                             cudaFuncAttributeMaxDynamicSharedMemorySize, AT_SMEM);
        attr_done = true;
    }

    __nv_bfloat16 *xhi, *xlo, *wqh, *wql, *wph, *wpl, *ahi, *alo;
    cudaGetSymbolAddress((void**)&xhi, g_xhi);
    cudaGetSymbolAddress((void**)&xlo, g_xlo);
    cudaGetSymbolAddress((void**)&wqh, g_wqkvT_hi);
    cudaGetSymbolAddress((void**)&wql, g_wqkvT_lo);
    cudaGetSymbolAddress((void**)&wph, g_wprojT_hi);
    cudaGetSymbolAddress((void**)&wpl, g_wprojT_lo);
    cudaGetSymbolAddress((void**)&ahi, g_att_hi);
    cudaGetSymbolAddress((void**)&alo, g_att_lo);

    // 1) input conversions
    convert_split_kernel<<<(SEQ * DMODEL / 4 + 255) / 256, 256>>>(x, xhi, xlo,
                                                                  SEQ * DMODEL / 4);
    convert_transpose_kernel<<<dim3(N_QKV / 32, DMODEL / 32), 256>>>(Wqkv, wqh, wql,
                                                                     DMODEL, N_QKV);
    convert_transpose_kernel<<<dim3(DMODEL / 32, DMODEL / 32), 256>>>(Wproj, wph, wpl,
                                                                      DMODEL, DMODEL);
    // 2) GEMM1: qkv = x @ Wqkv + bqkv (epilogue: Q/K split bf16, V fp32)
    mma_gemm_kernel<true><<<dim3(N_QKV / 128, SEQ / 128), 256, DYN_SMEM>>>(
        xhi, xlo, wqh, wql, bqkv, nullptr, N_QKV);
    // 3) V transpose + split
    transpose_v_kernel<<<dim3(SEQ / 32, HDIM / 32, NHEAD), 256>>>();
    // 4) attention -> g_att hi/lo
    attn_mma_kernel<<<dim3(SEQ / 128, NHEAD), 256, AT_SMEM>>>();
    // 5) GEMM2: out = att @ Wproj + bproj
    mma_gemm_kernel<false><<<dim3(DMODEL / 128, SEQ / 128), 256, DYN_SMEM>>>(
        ahi, alo, wph, wpl, bproj, out, DMODEL);
}

// round 6
// speedup vs baseline: 3.2396x; 1.0019x over previous
#include <cuda_runtime.h>
#include <cuda_bf16.h>
#include <cstdint>

// ---------------------------------------------------------------------------
// Attention_32186484917066 — R6: break HMMA RAW chains. Same math as R5, but
// MMAs issued in passes over distinct accumulators (reuse distance 8-16).
// ---------------------------------------------------------------------------

#define SEQ    4096
#define DMODEL 1024
#define NHEAD  16
#define HDIM   64
#define N_QKV  3072

// ------------------------- device scratch (no allocs) -----------------------
__device__ __align__(16) __nv_bfloat16 g_xhi[SEQ * DMODEL];
__device__ __align__(16) __nv_bfloat16 g_xlo[SEQ * DMODEL];
__device__ __align__(16) __nv_bfloat16 g_wqkvT_hi[N_QKV * DMODEL];   // [N][K]
__device__ __align__(16) __nv_bfloat16 g_wqkvT_lo[N_QKV * DMODEL];
__device__ __align__(16) __nv_bfloat16 g_wprojT_hi[DMODEL * DMODEL]; // [N][K]
__device__ __align__(16) __nv_bfloat16 g_wprojT_lo[DMODEL * DMODEL];
__device__ float g_qkv[3 * NHEAD * SEQ * HDIM];  // V region (part 2) used fp32
__device__ __align__(16) __nv_bfloat16 g_att_hi[SEQ * DMODEL];
__device__ __align__(16) __nv_bfloat16 g_att_lo[SEQ * DMODEL];
__device__ __align__(16) __nv_bfloat16 g_q_hi[NHEAD * SEQ * HDIM];   // [h][s][d]
__device__ __align__(16) __nv_bfloat16 g_q_lo[NHEAD * SEQ * HDIM];
__device__ __align__(16) __nv_bfloat16 g_k_hi[NHEAD * SEQ * HDIM];   // [h][s][d]
__device__ __align__(16) __nv_bfloat16 g_k_lo[NHEAD * SEQ * HDIM];
__device__ __align__(16) __nv_bfloat16 g_vt_hi[NHEAD * HDIM * SEQ];  // [h][d][s]
__device__ __align__(16) __nv_bfloat16 g_vt_lo[NHEAD * HDIM * SEQ];

// ------------------------- helpers -----------------------------------------
__device__ __forceinline__ uint32_t smem_u32(const void* p) {
    uint32_t a;
    asm("{ .reg .u64 t; cvta.to.shared.u64 t, %1; cvt.u32.u64 %0, t; }" : "=r"(a) : "l"(p));
    return a;
}
#define CP_ASYNC16(s, g) \
    asm volatile("cp.async.cg.shared.global [%0], [%1], 16;" :: "r"(s), "l"(g))
#define CP_COMMIT()  asm volatile("cp.async.commit_group;" ::: "memory")
#define CP_WAIT(n)   asm volatile("cp.async.wait_group %0;" :: "n"(n) : "memory")

__device__ __forceinline__ void mma16816(float* c, const uint32_t* a,
                                         uint32_t b0, uint32_t b1) {
    asm volatile(
        "mma.sync.aligned.m16n8k16.row.col.f32.bf16.bf16.f32 "
        "{%0,%1,%2,%3}, {%4,%5,%6,%7}, {%8,%9}, {%0,%1,%2,%3};"
        : "+f"(c[0]), "+f"(c[1]), "+f"(c[2]), "+f"(c[3])
        : "r"(a[0]), "r"(a[1]), "r"(a[2]), "r"(a[3]), "r"(b0), "r"(b1));
}
__device__ __forceinline__ void ldm_x4(uint32_t* r, uint32_t addr) {
    asm volatile("ldmatrix.sync.aligned.m8n8.x4.shared.b16 {%0,%1,%2,%3}, [%4];"
                 : "=r"(r[0]), "=r"(r[1]), "=r"(r[2]), "=r"(r[3]) : "r"(addr));
}
__device__ __forceinline__ float ex2f(float x) {
    float y;
    asm("ex2.approx.ftz.f32 %0, %1;" : "=f"(y) : "f"(x));
    return y;
}
__device__ __forceinline__ uint32_t pack_bf16_rn(float lo, float hi) {
    uint32_t r;
    asm("cvt.rn.bf16x2.f32 %0, %1, %2;" : "=r"(r) : "f"(hi), "f"(lo));
    return r;
}
__device__ __forceinline__ void split2(float2 v, uint32_t& hi, uint32_t& lo) {
    const uint32_t ux = __float_as_uint(v.x), uy = __float_as_uint(v.y);
    const float hx = __uint_as_float(ux & 0xffff0000u);
    const float hy = __uint_as_float(uy & 0xffff0000u);
    hi = __byte_perm(ux, uy, 0x7632);
    lo = pack_bf16_rn(v.x - hx, v.y - hy);
}

// ------------------------- conversion kernels ------------------------------
__global__ __launch_bounds__(256) void convert_split_kernel(
    const float* __restrict__ in, __nv_bfloat16* __restrict__ hi,
    __nv_bfloat16* __restrict__ lo, int n4)
{
    int i = blockIdx.x * 256 + threadIdx.x;
    if (i >= n4) return;
    float4 v = ((const float4*)in)[i];
    float vv[4] = {v.x, v.y, v.z, v.w};
    ushort4 h, l;
    unsigned short* hp = (unsigned short*)&h;
    unsigned short* lp = (unsigned short*)&l;
    #pragma unroll
    for (int j = 0; j < 4; j++) {
        __nv_bfloat16 bh = __float2bfloat16(vv[j]);
        float rem = vv[j] - __bfloat162float(bh);
        __nv_bfloat16 bl = __float2bfloat16(rem);
        hp[j] = *(unsigned short*)&bh;
        lp[j] = *(unsigned short*)&bl;
    }
    ((ushort4*)hi)[i] = h;
    ((ushort4*)lo)[i] = l;
}

// W[K][N] fp32 -> hi/lo [N][K] bf16 (transpose + split)
__global__ __launch_bounds__(256) void convert_transpose_kernel(
    const float* __restrict__ W, __nv_bfloat16* __restrict__ hi,
    __nv_bfloat16* __restrict__ lo, int K, int N)
{
    __shared__ float t[32][33];
    const int bn = blockIdx.x * 32, bk = blockIdx.y * 32;
    const int tx = threadIdx.x & 31, ty = threadIdx.x >> 5;
    #pragma unroll
    for (int r = 0; r < 32; r += 8)
        t[r + ty][tx] = W[(size_t)(bk + r + ty) * N + bn + tx];
    __syncthreads();
    #pragma unroll
    for (int r = 0; r < 32; r += 8) {
        float v = t[tx][r + ty];
        __nv_bfloat16 bh = __float2bfloat16(v);
        float rem = v - __bfloat162float(bh);
        __nv_bfloat16 bl = __float2bfloat16(rem);
        size_t o = (size_t)(bn + r + ty) * K + bk + tx;
        hi[o] = bh;
        lo[o] = bl;
    }
}

// transpose V (part 2 of g_qkv) per head: [s][d] -> [d][s], split hi/lo
__global__ __launch_bounds__(256) void transpose_v_kernel()
{
    __shared__ float t[32][33];
    const int s0 = blockIdx.x * 32;
    const int d0 = blockIdx.y * 32;
    const int h = blockIdx.z;
    const float* V = g_qkv + (size_t)(2 * NHEAD + h) * SEQ * HDIM;
    const int tx = threadIdx.x & 31, ty = threadIdx.x >> 5;
    #pragma unroll
    for (int r = 0; r < 32; r += 8)
        t[r + ty][tx] = V[(size_t)(s0 + r + ty) * HDIM + d0 + tx];
    __syncthreads();
    #pragma unroll
    for (int r = 0; r < 32; r += 8) {
        float v = t[tx][r + ty];
        __nv_bfloat16 bh = __float2bfloat16(v);
        float rem = v - __bfloat162float(bh);
        __nv_bfloat16 bl = __float2bfloat16(rem);
        size_t o = ((size_t)h * HDIM + d0 + r + ty) * SEQ + s0 + tx;
        g_vt_hi[o] = bh;
        g_vt_lo[o] = bl;
    }
}

// ------------------------- mma.sync GEMM ------------------------------------
// CTA 128x128, BK=32, 8 warps (32x64 warp tile), 3-stage cp.async, ldmatrix.
// Inner loop: 3 passes (hh/hl/lh) of 16 distinct-accumulator MMAs each.
#define GK       DMODEL
#define KITERS   (GK / 32)
#define MAT_B    (128 * 40 * 2)     // 10240, rows padded to 80B
#define STAGE_B  (4 * MAT_B)        // 40960
#define DYN_SMEM (3 * STAGE_B)      // 122880

template <bool QKV>
__global__ __launch_bounds__(256, 1) void mma_gemm_kernel(
    const __nv_bfloat16* __restrict__ Ahi, const __nv_bfloat16* __restrict__ Alo,
    const __nv_bfloat16* __restrict__ Bhi, const __nv_bfloat16* __restrict__ Blo,
    const float* __restrict__ bias, float* __restrict__ out, int N)
{
    extern __shared__ char sm[];
    const uint32_t sb = smem_u32(sm);

    const int tid  = threadIdx.x;
    const int lane = tid & 31;
    const int wid  = tid >> 5;
    const int gid  = lane >> 2;
    const int tig  = lane & 3;
    const int wm   = wid & 3;
    const int wn   = wid >> 2;

    const int bm = blockIdx.y * 128;
    const int bn = blockIdx.x * 128;

    const uint32_t aoff = (lane & 15) * 80 + (lane >> 4) * 16;
    const uint32_t boff = ((lane & 7) + (lane >> 4) * 8) * 80 + ((lane >> 3) & 1) * 16;

    auto issue_stage = [&](int stage, int kt) {
        const uint32_t stb = sb + stage * STAGE_B;
        #pragma unroll
        for (int mat = 0; mat < 4; mat++) {
            const __nv_bfloat16* base =
                (mat == 0) ? Ahi : (mat == 1) ? Alo : (mat == 2) ? Bhi : Blo;
            const int r0 = (mat < 2) ? bm : bn;
            #pragma unroll
            for (int p = 0; p < 2; p++) {
                const int idx = p * 256 + tid;
                const int row = idx >> 2;
                const int c   = idx & 3;
                const char* g = (const char*)(base + (size_t)(r0 + row) * GK
                                              + kt * 32 + c * 8);
                CP_ASYNC16(stb + mat * MAT_B + row * 80 + c * 16, g);
            }
        }
    };

    float acc[2][8][4] = {};

    issue_stage(0, 0);
    CP_COMMIT();
    issue_stage(1, 1);
    CP_COMMIT();

    for (int kt = 0; kt < KITERS; kt++) {
        if (kt + 1 < KITERS) { CP_WAIT(1); } else { CP_WAIT(0); }
        __syncthreads();
        if (kt + 2 < KITERS) {
            issue_stage((kt + 2) % 3, kt + 2);
            CP_COMMIT();
        }

        const uint32_t stg = sb + (kt % 3) * STAGE_B;
        const uint32_t bAh = stg;
        const uint32_t bAl = stg + MAT_B;
        const uint32_t bBh = stg + 2 * MAT_B;
        const uint32_t bBl = stg + 3 * MAT_B;

        #pragma unroll
        for (int ks = 0; ks < 2; ks++) {
            uint32_t ah[2][4], al[2][4];
            ldm_x4(ah[0], bAh + (wm * 32) * 80 + ks * 32 + aoff);
            ldm_x4(ah[1], bAh + (wm * 32 + 16) * 80 + ks * 32 + aoff);
            ldm_x4(al[0], bAl + (wm * 32) * 80 + ks * 32 + aoff);
            ldm_x4(al[1], bAl + (wm * 32 + 16) * 80 + ks * 32 + aoff);
            uint32_t bh[4][4], bl[4][4];
            #pragma unroll
            for (int ntp = 0; ntp < 4; ntp++) {
                ldm_x4(bh[ntp], bBh + (wn * 64 + ntp * 16) * 80 + ks * 32 + boff);
                ldm_x4(bl[ntp], bBl + (wn * 64 + ntp * 16) * 80 + ks * 32 + boff);
            }
            // pass 1: hi*hi — 16 distinct accumulators
            #pragma unroll
            for (int ntp = 0; ntp < 4; ntp++)
                #pragma unroll
                for (int mt = 0; mt < 2; mt++) {
                    mma16816(acc[mt][2 * ntp],     ah[mt], bh[ntp][0], bh[ntp][1]);
                    mma16816(acc[mt][2 * ntp + 1], ah[mt], bh[ntp][2], bh[ntp][3]);
                }
            // pass 2: hi*lo
            #pragma unroll
            for (int ntp = 0; ntp < 4; ntp++)
                #pragma unroll
                for (int mt = 0; mt < 2; mt++) {
                    mma16816(acc[mt][2 * ntp],     ah[mt], bl[ntp][0], bl[ntp][1]);
                    mma16816(acc[mt][2 * ntp + 1], ah[mt], bl[ntp][2], bl[ntp][3]);
                }
            // pass 3: lo*hi
            #pragma unroll
            for (int ntp = 0; ntp < 4; ntp++)
                #pragma unroll
                for (int mt = 0; mt < 2; mt++) {
                    mma16816(acc[mt][2 * ntp],     al[mt], bh[ntp][0], bh[ntp][1]);
                    mma16816(acc[mt][2 * ntp + 1], al[mt], bh[ntp][2], bh[ntp][3]);
                }
        }
    }

    // epilogue
    #pragma unroll
    for (int mt = 0; mt < 2; mt++) {
        const int r = bm + wm * 32 + mt * 16 + gid;
        #pragma unroll
        for (int nt = 0; nt < 8; nt++) {
            const int col = bn + wn * 64 + nt * 8 + tig * 2;
            const float2 bv = *(const float2*)&bias[col];
            float2 d0, d1;
            d0.x = acc[mt][nt][0] + bv.x;
            d0.y = acc[mt][nt][1] + bv.y;
            d1.x = acc[mt][nt][2] + bv.x;
            d1.y = acc[mt][nt][3] + bv.y;
            if (QKV) {
                const int part = col >> 10;
                const int hh = (col >> 6) & 15;
                const int d = col & 63;
                if (part < 2) {
                    __nv_bfloat16* dh = part ? g_k_hi : g_q_hi;
                    __nv_bfloat16* dl = part ? g_k_lo : g_q_lo;
                    const size_t i0 = ((size_t)hh * SEQ + r) * HDIM + d;
                    uint32_t hi, lo;
                    split2(d0, hi, lo);
                    *(uint32_t*)&dh[i0] = hi;
                    *(uint32_t*)&dl[i0] = lo;
                    split2(d1, hi, lo);
                    *(uint32_t*)&dh[i0 + 8 * HDIM] = hi;
                    *(uint32_t*)&dl[i0 + 8 * HDIM] = lo;
                } else {
                    float* dst = g_qkv + (((size_t)(2 * NHEAD + hh) * SEQ + r) << 6) + d;
                    *(float2*)dst = d0;
                    *(float2*)(dst + 8 * 64) = d1;
                }
            } else {
                float* dst = out + (size_t)r * N + col;
                *(float2*)dst = d0;
                *(float2*)(dst + 8 * (size_t)N) = d1;
            }
        }
    }
}

// ---------------------------------------------------------------------------
// Flash attention on mma.sync + ldmatrix, pass-reordered MMAs.
// ---------------------------------------------------------------------------
#define AT_MAT_B   9216                  // 64 * 144
#define AT_STAGE_B (4 * AT_MAT_B)        // 36864
#define AT_Q_B     (2 * 128 * 144)       // 36864
#define AT_SMEM    (3 * AT_STAGE_B + AT_Q_B)  // 147456

__global__ __launch_bounds__(256, 1) void attn_mma_kernel()
{
    extern __shared__ char sm[];
    const uint32_t sb = smem_u32(sm);
    const uint32_t qbase = sb + 3 * AT_STAGE_B;

    const int tid  = threadIdx.x;
    const int lane = tid & 31;
    const int w    = tid >> 5;
    const int gid  = lane >> 2;
    const int tig  = lane & 3;

    const int qt = 31 - blockIdx.x;
    const int h  = blockIdx.y;
    const int q0 = qt * 128;
    const int wq0 = q0 + w * 16;
    const int ktmax = 2 * qt + 1;

    const uint32_t boff = ((lane & 7) + (lane >> 4) * 8) * 144 + ((lane >> 3) & 1) * 16;

    auto load_kv = [&](int stage, int kt) {
        const uint32_t stb = sb + stage * AT_STAGE_B;
        #pragma unroll
        for (int t = 0; t < 8; t++) {
            const int mat = t >> 1;
            const int within = (t & 1) * 256 + tid;
            const int row = within >> 3;
            const int ch = within & 7;
            const __nv_bfloat16* src;
            if (mat == 0)
                src = g_k_hi + ((size_t)h * SEQ + kt * 64 + row) * HDIM + ch * 8;
            else if (mat == 1)
                src = g_k_lo + ((size_t)h * SEQ + kt * 64 + row) * HDIM + ch * 8;
            else if (mat == 2)
                src = g_vt_hi + ((size_t)h * HDIM + row) * SEQ + kt * 64 + ch * 8;
            else
                src = g_vt_lo + ((size_t)h * HDIM + row) * SEQ + kt * 64 + ch * 8;
            CP_ASYNC16(stb + mat * AT_MAT_B + row * 144 + ch * 16, src);
        }
    };

    // ---- prologue
    {
        const __nv_bfloat16* Qh = g_q_hi + ((size_t)h * SEQ + q0) * HDIM;
        const __nv_bfloat16* Ql = g_q_lo + ((size_t)h * SEQ + q0) * HDIM;
        #pragma unroll
        for (int t = 0; t < 8; t++) {
            const int mat = t >> 2;
            const int within = (t & 3) * 256 + tid;
            const int row = within >> 3;
            const int ch = within & 7;
            const __nv_bfloat16* src = (mat ? Ql : Qh) + (size_t)row * HDIM + ch * 8;
            CP_ASYNC16(qbase + mat * 18432 + row * 144 + ch * 16, src);
        }
        CP_COMMIT();
    }
    load_kv(0, 0);
    CP_COMMIT();
    if (ktmax >= 1) { load_kv(1, 1); CP_COMMIT(); }

    if (ktmax >= 1) { CP_WAIT(2); } else { CP_WAIT(1); }
    __syncthreads();

    uint32_t qh[4][4], ql[4][4];
    {
        const uint32_t aoff = (lane & 15) * 144 + (lane >> 4) * 16;
        #pragma unroll
        for (int ki = 0; ki < 4; ki++) {
            ldm_x4(qh[ki], qbase + (w * 16) * 144 + ki * 32 + aoff);
            ldm_x4(ql[ki], qbase + 18432 + (w * 16) * 144 + ki * 32 + aoff);
        }
    }

    float o[8][4] = {};
    float m0 = -1e30f, m1 = -1e30f, l0 = 0.0f, l1 = 0.0f;
    const float SC = 0.1803368801111244f;  // 0.125 * log2(e)

    for (int kt = 0; kt <= ktmax; kt++) {
        if (kt + 1 <= ktmax) { CP_WAIT(1); } else { CP_WAIT(0); }
        __syncthreads();
        if (kt + 2 <= ktmax) {
            load_kv((kt + 2) % 3, kt + 2);
            CP_COMMIT();
        }

        const int kc0 = kt * 64;
        if (kc0 > wq0 + 15) continue;

        const uint32_t stg = sb + (kt % 3) * AT_STAGE_B;
        const uint32_t bKh = stg;
        const uint32_t bKl = stg + AT_MAT_B;
        const uint32_t bVh = stg + 2 * AT_MAT_B;
        const uint32_t bVl = stg + 3 * AT_MAT_B;

        // ---- S = Q K^T: ki outer, 3 passes of 8 distinct-acc MMAs per ki
        float s[8][4] = {};
        #pragma unroll
        for (int ki = 0; ki < 4; ki++) {
            uint32_t bh[4][4], bl[4][4];
            #pragma unroll
            for (int ntp = 0; ntp < 4; ntp++) {
                ldm_x4(bh[ntp], bKh + (ntp * 16) * 144 + ki * 32 + boff);
                ldm_x4(bl[ntp], bKl + (ntp * 16) * 144 + ki * 32 + boff);
            }
            #pragma unroll
            for (int ntp = 0; ntp < 4; ntp++) {
                mma16816(s[2 * ntp],     qh[ki], bh[ntp][0], bh[ntp][1]);
                mma16816(s[2 * ntp + 1], qh[ki], bh[ntp][2], bh[ntp][3]);
            }
            #pragma unroll
            for (int ntp = 0; ntp < 4; ntp++) {
                mma16816(s[2 * ntp],     qh[ki], bl[ntp][0], bl[ntp][1]);
                mma16816(s[2 * ntp + 1], qh[ki], bl[ntp][2], bl[ntp][3]);
            }
            #pragma unroll
            for (int ntp = 0; ntp < 4; ntp++) {
                mma16816(s[2 * ntp],     ql[ki], bh[ntp][0], bh[ntp][1]);
                mma16816(s[2 * ntp + 1], ql[ki], bh[ntp][2], bh[ntp][3]);
            }
        }

        // scale + causal mask
        const bool partial = (kc0 + 63) > wq0;
        const int r0 = wq0 + gid, r1 = r0 + 8;
        #pragma unroll
        for (int nt = 0; nt < 8; nt++) {
            const int cb = kc0 + nt * 8 + tig * 2;
            s[nt][0] *= SC; s[nt][1] *= SC; s[nt][2] *= SC; s[nt][3] *= SC;
            if (partial) {
                if (cb > r0)     s[nt][0] = -1e30f;
                if (cb + 1 > r0) s[nt][1] = -1e30f;
                if (cb > r1)     s[nt][2] = -1e30f;
                if (cb + 1 > r1) s[nt][3] = -1e30f;
            }
        }

        // online softmax
        float mx0 = -1e30f, mx1 = -1e30f;
        #pragma unroll
        for (int nt = 0; nt < 8; nt++) {
            mx0 = fmaxf(mx0, fmaxf(s[nt][0], s[nt][1]));
            mx1 = fmaxf(mx1, fmaxf(s[nt][2], s[nt][3]));
        }
        mx0 = fmaxf(mx0, __shfl_xor_sync(0xffffffffu, mx0, 1));
        mx0 = fmaxf(mx0, __shfl_xor_sync(0xffffffffu, mx0, 2));
        mx1 = fmaxf(mx1, __shfl_xor_sync(0xffffffffu, mx1, 1));
        mx1 = fmaxf(mx1, __shfl_xor_sync(0xffffffffu, mx1, 2));

        const float nm0 = fmaxf(m0, mx0);
        const float nm1 = fmaxf(m1, mx1);
        const float f0 = ex2f(m0 - nm0);
        const float f1 = ex2f(m1 - nm1);
        m0 = nm0; m1 = nm1;

        uint32_t pah[4][4], pal[4][4];
        float rs0 = 0.0f, rs1 = 0.0f;
        #pragma unroll
        for (int j = 0; j < 4; j++) {
            #pragma unroll
            for (int half = 0; half < 2; half++) {
                const int nt = 2 * j + half;
                float p0 = ex2f(s[nt][0] - nm0);
                float p1 = ex2f(s[nt][1] - nm0);
                float p2 = ex2f(s[nt][2] - nm1);
                float p3 = ex2f(s[nt][3] - nm1);
                rs0 += p0 + p1;
                rs1 += p2 + p3;
                uint32_t u0 = __float_as_uint(p0), u1 = __float_as_uint(p1);
                uint32_t u2 = __float_as_uint(p2), u3 = __float_as_uint(p3);
                float h0 = __uint_as_float(u0 & 0xffff0000u);
                float h1 = __uint_as_float(u1 & 0xffff0000u);
                float h2 = __uint_as_float(u2 & 0xffff0000u);
                float h3 = __uint_as_float(u3 & 0xffff0000u);
                pah[j][0 + 2 * half] = __byte_perm(u0, u1, 0x7632);
                pah[j][1 + 2 * half] = __byte_perm(u2, u3, 0x7632);
                pal[j][0 + 2 * half] = pack_bf16_rn(p0 - h0, p1 - h1);
                pal[j][1 + 2 * half] = pack_bf16_rn(p2 - h2, p3 - h3);
            }
        }
        rs0 += __shfl_xor_sync(0xffffffffu, rs0, 1);
        rs0 += __shfl_xor_sync(0xffffffffu, rs0, 2);
        rs1 += __shfl_xor_sync(0xffffffffu, rs1, 1);
        rs1 += __shfl_xor_sync(0xffffffffu, rs1, 2);
        l0 = l0 * f0 + rs0;
        l1 = l1 * f1 + rs1;

        #pragma unroll
        for (int nt = 0; nt < 8; nt++) {
            o[nt][0] *= f0; o[nt][1] *= f0;
            o[nt][2] *= f1; o[nt][3] *= f1;
        }

        // ---- O += P V: j outer, 3 passes of 8 distinct-acc MMAs per j
        #pragma unroll
        for (int j = 0; j < 4; j++) {
            uint32_t vh[4][4], vl[4][4];
            #pragma unroll
            for (int ntp = 0; ntp < 4; ntp++) {
                ldm_x4(vh[ntp], bVh + (ntp * 16) * 144 + j * 32 + boff);
                ldm_x4(vl[ntp], bVl + (ntp * 16) * 144 + j * 32 + boff);
            }
            #pragma unroll
            for (int ntp = 0; ntp < 4; ntp++) {
                mma16816(o[2 * ntp],     pah[j], vh[ntp][0], vh[ntp][1]);
                mma16816(o[2 * ntp + 1], pah[j], vh[ntp][2], vh[ntp][3]);
            }
            #pragma unroll
            for (int ntp = 0; ntp < 4; ntp++) {
                mma16816(o[2 * ntp],     pal[j], vh[ntp][0], vh[ntp][1]);
                mma16816(o[2 * ntp + 1], pal[j], vh[ntp][2], vh[ntp][3]);
            }
            #pragma unroll
            for (int ntp = 0; ntp < 4; ntp++) {
                mma16816(o[2 * ntp],     pah[j], vl[ntp][0], vl[ntp][1]);
                mma16816(o[2 * ntp + 1], pah[j], vl[ntp][2], vl[ntp][3]);
            }
        }
    }

    // ---- epilogue
    const float inv0 = 1.0f / l0;
    const float inv1 = 1.0f / l1;
    #pragma unroll
    for (int nt = 0; nt < 8; nt++) {
        const int col = h * HDIM + nt * 8 + tig * 2;
        {
            float2 v = make_float2(o[nt][0] * inv0, o[nt][1] * inv0);
            uint32_t hi, lo;
            split2(v, hi, lo);
            const size_t off = (size_t)(wq0 + gid) * DMODEL + col;
            *(uint32_t*)&g_att_hi[off] = hi;
            *(uint32_t*)&g_att_lo[off] = lo;
        }
        {
            float2 v = make_float2(o[nt][2] * inv1, o[nt][3] * inv1);
            uint32_t hi, lo;
            split2(v, hi, lo);
            const size_t off = (size_t)(wq0 + gid + 8) * DMODEL + col;
            *(uint32_t*)&g_att_hi[off] = hi;
            *(uint32_t*)&g_att_lo[off] = lo;
        }
    }
}

// ---------------------------------------------------------------------------
extern "C" void kernel_launch(void* const* d_in, const int* in_sizes, int n_in,
                              void* d_out, int out_size)
{
    const float* x     = (const float*)d_in[0];
    const float* Wqkv  = (const float*)d_in[1];
    const float* bqkv  = (const float*)d_in[2];
    const float* Wproj = (const float*)d_in[3];
    const float* bproj = (const float*)d_in[4];
    float* out = (float*)d_out;

    static bool attr_done = false;
    if (!attr_done) {
        cudaFuncSetAttribute(mma_gemm_kernel<true>,
                             cudaFuncAttributeMaxDynamicSharedMemorySize, DYN_SMEM);
        cudaFuncSetAttribute(mma_gemm_kernel<false>,
                             cudaFuncAttributeMaxDynamicSharedMemorySize, DYN_SMEM);
        cudaFuncSetAttribute(attn_mma_kernel,
                             cudaFuncAttributeMaxDynamicSharedMemorySize, AT_SMEM);
        attr_done = true;
    }

    __nv_bfloat16 *xhi, *xlo, *wqh, *wql, *wph, *wpl, *ahi, *alo;
    cudaGetSymbolAddress((void**)&xhi, g_xhi);
    cudaGetSymbolAddress((void**)&xlo, g_xlo);
    cudaGetSymbolAddress((void**)&wqh, g_wqkvT_hi);
    cudaGetSymbolAddress((void**)&wql, g_wqkvT_lo);
    cudaGetSymbolAddress((void**)&wph, g_wprojT_hi);
    cudaGetSymbolAddress((void**)&wpl, g_wprojT_lo);
    cudaGetSymbolAddress((void**)&ahi, g_att_hi);
    cudaGetSymbolAddress((void**)&alo, g_att_lo);

    // 1) input conversions
    convert_split_kernel<<<(SEQ * DMODEL / 4 + 255) / 256, 256>>>(x, xhi, xlo,
                                                                  SEQ * DMODEL / 4);
    convert_transpose_kernel<<<dim3(N_QKV / 32, DMODEL / 32), 256>>>(Wqkv, wqh, wql,
                                                                     DMODEL, N_QKV);
    convert_transpose_kernel<<<dim3(DMODEL / 32, DMODEL / 32), 256>>>(Wproj, wph, wpl,
                                                                      DMODEL, DMODEL);
    // 2) GEMM1: qkv = x @ Wqkv + bqkv (epilogue: Q/K split bf16, V fp32)
    mma_gemm_kernel<true><<<dim3(N_QKV / 128, SEQ / 128), 256, DYN_SMEM>>>(
        xhi, xlo, wqh, wql, bqkv, nullptr, N_QKV);
    // 3) V transpose + split
    transpose_v_kernel<<<dim3(SEQ / 32, HDIM / 32, NHEAD), 256>>>();
    // 4) attention -> g_att hi/lo
    attn_mma_kernel<<<dim3(SEQ / 128, NHEAD), 256, AT_SMEM>>>();
    // 5) GEMM2: out = att @ Wproj + bproj
    mma_gemm_kernel<false><<<dim3(DMODEL / 128, SEQ / 128), 256, DYN_SMEM>>>(
        ahi, alo, wph, wpl, bproj, out, DMODEL);
}